// round 6
// baseline (speedup 1.0000x reference)
#include <cuda_runtime.h>
#include <cuda_bf16.h>
#include <math.h>
#include <cstdint>

// Problem constants: B=2, S=2048, D=1024, H=16, HD=64
#define B_  2
#define S_  2048
#define D_  1024
#define H_  16
#define HD_ 64
#define SCALE_ 0.03125f   // D^-0.5 (reference scales by full input dim)
#define KTOT 1024

// ---------------------------------------------------------------------------
// Scratch (device globals; no dynamic allocation allowed)
// ---------------------------------------------------------------------------
__device__ float g_q[(size_t)B_*H_*S_*HD_];     // [B,H,S,HD] fp32
__device__ float g_k[(size_t)B_*H_*S_*HD_];
__device__ float g_v[(size_t)B_*H_*S_*HD_];
__device__ float g_att[(size_t)B_*S_*D_];       // concat heads [B,S,D] fp32

// bf16 hi/lo split buffers
__device__ __nv_bfloat16 g_xh[(size_t)B_*S_*D_],  g_xl[(size_t)B_*S_*D_];       // x    [4096,1024]
__device__ __nv_bfloat16 g_atth[(size_t)B_*S_*D_],g_attl[(size_t)B_*S_*D_];     // att  [4096,1024]
__device__ __nv_bfloat16 g_wbh[(size_t)3*H_*HD_*D_], g_wbl[(size_t)3*H_*HD_*D_];// Wqkv^T [3072,1024]
__device__ __nv_bfloat16 g_wph[(size_t)D_*D_],    g_wpl[(size_t)D_*D_];         // Wp   [1024,1024]

// ---------------------------------------------------------------------------
// PTX helpers (sm_80+ instructions only — compile clean under compute_103)
// ---------------------------------------------------------------------------
__device__ __forceinline__ uint32_t smem_to_u32(const void* p) {
    uint32_t a;
    asm("{ .reg .u64 t; cvta.to.shared.u64 t, %1; cvt.u32.u64 %0, t; }" : "=r"(a) : "l"(p));
    return a;
}
#define LDSM4(r, addr) \
    asm volatile("ldmatrix.sync.aligned.m8n8.x4.shared.b16 {%0,%1,%2,%3}, [%4];" \
        : "=r"((r)[0]), "=r"((r)[1]), "=r"((r)[2]), "=r"((r)[3]) : "r"(addr))
#define MMA_BF16(c, a, b0, b1) \
    asm volatile("mma.sync.aligned.m16n8k16.row.col.f32.bf16.bf16.f32 " \
        "{%0,%1,%2,%3}, {%4,%5,%6,%7}, {%8,%9}, {%0,%1,%2,%3};" \
        : "+f"((c)[0]), "+f"((c)[1]), "+f"((c)[2]), "+f"((c)[3]) \
        : "r"((a)[0]), "r"((a)[1]), "r"((a)[2]), "r"((a)[3]), "r"(b0), "r"(b1))

// ---------------------------------------------------------------------------
// Split kernels: fp32 -> bf16 (hi) + bf16 (residual lo)
// mode: 0 = x (src param) -> g_xh/g_xl
//       1 = g_att         -> g_atth/g_attl
//       2 = Wp (src param)-> g_wph/g_wpl
// ---------------------------------------------------------------------------
__global__ __launch_bounds__(256) void split_kernel(const float* __restrict__ src,
                                                    int mode, int n4)
{
    int i = blockIdx.x * 256 + threadIdx.x;
    if (i >= n4) return;
    const float* s = (mode == 1) ? g_att : src;
    __nv_bfloat16* dh = (mode == 0) ? g_xh : (mode == 1) ? g_atth : g_wph;
    __nv_bfloat16* dl = (mode == 0) ? g_xl : (mode == 1) ? g_attl : g_wpl;

    float4 v = ((const float4*)s)[i];
    __nv_bfloat16 h0 = __float2bfloat16(v.x);
    __nv_bfloat16 h1 = __float2bfloat16(v.y);
    __nv_bfloat16 h2 = __float2bfloat16(v.z);
    __nv_bfloat16 h3 = __float2bfloat16(v.w);
    __nv_bfloat16 l0 = __float2bfloat16(v.x - __bfloat162float(h0));
    __nv_bfloat16 l1 = __float2bfloat16(v.y - __bfloat162float(h1));
    __nv_bfloat16 l2 = __float2bfloat16(v.z - __bfloat162float(h2));
    __nv_bfloat16 l3 = __float2bfloat16(v.w - __bfloat162float(h3));
    __nv_bfloat16 hs[4] = {h0, h1, h2, h3};
    __nv_bfloat16 ls[4] = {l0, l1, l2, l3};
    ((uint2*)dh)[i] = *(uint2*)hs;
    ((uint2*)dl)[i] = *(uint2*)ls;
}

// Build B matrix for QKV: rows n = which*1024 + h*64 + e, cols k.
// B[n][k] = W_sel[h][k][e], split into hi/lo bf16.
__global__ __launch_bounds__(256) void convw_kernel(const float* __restrict__ Wq,
                                                    const float* __restrict__ Wk,
                                                    const float* __restrict__ Wv)
{
    size_t idx = (size_t)blockIdx.x * 256 + threadIdx.x;   // over 3072*1024
    int n = (int)(idx >> 10);
    int k = (int)(idx & 1023);
    int which = n >> 10;
    int h = (n >> 6) & 15;
    int e = n & 63;
    const float* W = (which == 0 ? Wq : which == 1 ? Wk : Wv);
    float v = W[((size_t)h * D_ + k) * HD_ + e];
    __nv_bfloat16 hi = __float2bfloat16(v);
    __nv_bfloat16 lo = __float2bfloat16(v - __bfloat162float(hi));
    g_wbh[idx] = hi;
    g_wbl[idx] = lo;
}

// ---------------------------------------------------------------------------
// Warp-MMA GEMM (HMMA via mma.sync, bf16x3 split, fp32 accumulate in regs).
// C[m0+128, n0+128] = A[128,1024] @ B[N,1024]^T
// 256 threads = 8 warps, warp grid 2(M) x 4(N): warp tile 64x32.
// BK = 32 per stage; smem tiles padded to stride 40 bf16 (80B rows).
// mode 0: QKV  (A = x split, B = Wqkv^T split, scatter to g_q/g_k/g_v)
// mode 1: proj (A = att split, B = Wp split, C row-major + bias)
// ---------------------------------------------------------------------------
#define SPAD 40

__global__ __launch_bounds__(256) void gemm_mma(int mode,
                                                const float* __restrict__ bias,
                                                float* __restrict__ Cout)
{
    __shared__ __nv_bfloat16 sAh[128 * SPAD], sAl[128 * SPAD];
    __shared__ __nv_bfloat16 sBh[128 * SPAD], sBl[128 * SPAD];

    const int tid  = threadIdx.x;
    const int lane = tid & 31;
    const int wid  = tid >> 5;
    const int warp_m = wid >> 2;       // 0..1
    const int warp_n = wid & 3;        // 0..3
    const int n0 = blockIdx.x * 128;
    const int m0 = blockIdx.y * 128;

    const __nv_bfloat16* Ah = mode ? g_atth : g_xh;
    const __nv_bfloat16* Al = mode ? g_attl : g_xl;
    const __nv_bfloat16* Bh = mode ? g_wph  : g_wbh;
    const __nv_bfloat16* Bl = mode ? g_wpl  : g_wbl;

    // global load assignment: thread -> (row, 16-elem segment)
    const int lrow = tid >> 1;         // 0..127
    const int lseg = tid & 1;          // 0..1 (elems lseg*16 .. +15)
    const __nv_bfloat16* gah = Ah + (size_t)(m0 + lrow) * KTOT + lseg * 16;
    const __nv_bfloat16* gal = Al + (size_t)(m0 + lrow) * KTOT + lseg * 16;
    const __nv_bfloat16* gbh = Bh + (size_t)(n0 + lrow) * KTOT + lseg * 16;
    const __nv_bfloat16* gbl = Bl + (size_t)(n0 + lrow) * KTOT + lseg * 16;

    const uint32_t uAh = smem_to_u32(sAh), uAl = smem_to_u32(sAl);
    const uint32_t uBh = smem_to_u32(sBh), uBl = smem_to_u32(sBl);

    // ldmatrix per-lane addressing components
    const int lrm = lane & 15;          // row within 16-row tile
    const int lck = (lane >> 4) * 8;    // 8-elem k chunk

    float acc[4][4][4];
    #pragma unroll
    for (int i = 0; i < 4; i++)
        #pragma unroll
        for (int j = 0; j < 4; j++)
            #pragma unroll
            for (int r = 0; r < 4; r++) acc[i][j][r] = 0.f;

    const int sbase = lrow * SPAD + lseg * 16;

    for (int kc = 0; kc < KTOT / 32; kc++) {
        // stage BK=32 of all four tiles
        #pragma unroll
        for (int c = 0; c < 2; c++) {
            *(uint4*)&sAh[sbase + c * 8] = ((const uint4*)gah)[c];
            *(uint4*)&sAl[sbase + c * 8] = ((const uint4*)gal)[c];
            *(uint4*)&sBh[sbase + c * 8] = ((const uint4*)gbh)[c];
            *(uint4*)&sBl[sbase + c * 8] = ((const uint4*)gbl)[c];
        }
        __syncthreads();

        #pragma unroll
        for (int ks = 0; ks < 2; ks++) {
            const int koff = ks * 16 + lck;
            uint32_t afh[4][4], afl[4][4];
            uint32_t bfh[2][4], bfl[2][4];
            #pragma unroll
            for (int mt = 0; mt < 4; mt++) {
                const uint32_t off = 2u * ((warp_m * 64 + mt * 16 + lrm) * SPAD + koff);
                LDSM4(afh[mt], uAh + off);
                LDSM4(afl[mt], uAl + off);
            }
            #pragma unroll
            for (int np = 0; np < 2; np++) {
                const uint32_t off = 2u * ((warp_n * 32 + np * 16 + lrm) * SPAD + koff);
                LDSM4(bfh[np], uBh + off);
                LDSM4(bfl[np], uBl + off);
            }
            #pragma unroll
            for (int mt = 0; mt < 4; mt++) {
                #pragma unroll
                for (int nt = 0; nt < 4; nt++) {
                    const int np = nt >> 1, sel = nt & 1;
                    // hi*hi + hi*lo + lo*hi (lo*lo negligible)
                    MMA_BF16(acc[mt][nt], afh[mt], bfh[np][sel], bfh[np][sel + 2]);
                    MMA_BF16(acc[mt][nt], afh[mt], bfl[np][sel], bfl[np][sel + 2]);
                    MMA_BF16(acc[mt][nt], afl[mt], bfh[np][sel], bfh[np][sel + 2]);
                }
            }
        }
        __syncthreads();
        gah += 32; gal += 32; gbh += 32; gbl += 32;
    }

    // ------------------------------ epilogue ------------------------------
    #pragma unroll
    for (int mt = 0; mt < 4; mt++) {
        #pragma unroll
        for (int nt = 0; nt < 4; nt++) {
            const int mrow = m0 + warp_m * 64 + mt * 16 + (lane >> 2);
            const int ncol = n0 + warp_n * 32 + nt * 8 + (lane & 3) * 2;
            if (mode == 1) {
                const float b0 = bias[ncol], b1 = bias[ncol + 1];
                float2 v0 = make_float2(acc[mt][nt][0] + b0, acc[mt][nt][1] + b1);
                float2 v1 = make_float2(acc[mt][nt][2] + b0, acc[mt][nt][3] + b1);
                *(float2*)(Cout + (size_t)mrow * D_ + ncol)       = v0;
                *(float2*)(Cout + (size_t)(mrow + 8) * D_ + ncol) = v1;
            } else {
                const int which = ncol >> 10;
                const int h = (ncol >> 6) & 15;
                const int e = ncol & 63;
                float* base = (which == 0 ? g_q : which == 1 ? g_k : g_v);
                const int b0i = mrow >> 11, s0 = mrow & 2047;
                const int b1i = (mrow + 8) >> 11, s1 = (mrow + 8) & 2047;
                float* d0 = base + (((size_t)(b0i * H_ + h) * S_) + s0) * HD_ + e;
                float* d1 = base + (((size_t)(b1i * H_ + h) * S_) + s1) * HD_ + e;
                *(float2*)d0 = make_float2(acc[mt][nt][0], acc[mt][nt][1]);
                *(float2*)d1 = make_float2(acc[mt][nt][2], acc[mt][nt][3]);
            }
        }
    }
}

// ---------------------------------------------------------------------------
// Kernel 2: causal flash attention, fp32 (unchanged, known-good).
// ---------------------------------------------------------------------------
__global__ __launch_bounds__(64) void attn_kernel()
{
    const int qt  = blockIdx.x;     // 0..S/64-1
    const int bh  = blockIdx.y;     // 0..B*H-1
    const int row = threadIdx.x;    // 0..63

    const float* Qb = g_q + (size_t)bh * S_ * HD_;
    const float* Kb = g_k + (size_t)bh * S_ * HD_;
    const float* Vb = g_v + (size_t)bh * S_ * HD_;

    __shared__ float q_s[64 * 64];
    __shared__ float kT [64 * 64];
    __shared__ float v_s[64 * 64];

    {
        const float4* src = (const float4*)(Qb + (size_t)qt * 64 * HD_);
        float4* dst = (float4*)q_s;
        #pragma unroll
        for (int i = 0; i < 16; i++) dst[row + i * 64] = src[row + i * 64];
    }

    float acc[64];
    #pragma unroll
    for (int e = 0; e < 64; e++) acc[e] = 0.f;
    float m_i = -1e30f, l_i = 0.f;

    const int ntiles = qt + 1;
    for (int tile = 0; tile < ntiles; tile++) {
        const int j0 = tile * 64;
        __syncthreads();

        {
            const float4* krow = (const float4*)(Kb + (size_t)(j0 + row) * HD_);
            #pragma unroll
            for (int dq = 0; dq < 16; dq++) {
                float4 k4 = krow[dq];
                kT[(dq * 4 + 0) * 64 + row] = k4.x;
                kT[(dq * 4 + 1) * 64 + row] = k4.y;
                kT[(dq * 4 + 2) * 64 + row] = k4.z;
                kT[(dq * 4 + 3) * 64 + row] = k4.w;
            }
            const float4* vsrc = (const float4*)(Vb + (size_t)j0 * HD_);
            float4* vdst = (float4*)v_s;
            #pragma unroll
            for (int i = 0; i < 16; i++) vdst[row + i * 64] = vsrc[row + i * 64];
        }
        __syncthreads();

        float s[64];
        #pragma unroll
        for (int j = 0; j < 64; j++) s[j] = 0.f;
        #pragma unroll 1
        for (int d0 = 0; d0 < 64; d0 += 4) {
            float4 qv = *(float4*)&q_s[row * 64 + d0];
            #pragma unroll
            for (int j = 0; j < 64; j += 4) {
                float4 ka = *(float4*)&kT[(d0 + 0) * 64 + j];
                float4 kb = *(float4*)&kT[(d0 + 1) * 64 + j];
                float4 kc = *(float4*)&kT[(d0 + 2) * 64 + j];
                float4 kd = *(float4*)&kT[(d0 + 3) * 64 + j];
                s[j + 0] += qv.x * ka.x + qv.y * kb.x + qv.z * kc.x + qv.w * kd.x;
                s[j + 1] += qv.x * ka.y + qv.y * kb.y + qv.z * kc.y + qv.w * kd.y;
                s[j + 2] += qv.x * ka.z + qv.y * kb.z + qv.z * kc.z + qv.w * kd.z;
                s[j + 3] += qv.x * ka.w + qv.y * kb.w + qv.z * kc.w + qv.w * kd.w;
            }
        }

        const bool diag = (tile == qt);

        float mn = m_i;
        #pragma unroll
        for (int j = 0; j < 64; j++) {
            float tv = s[j] * SCALE_;
            if (diag && j > row) tv = -1e30f;
            s[j] = tv;
            mn = fmaxf(mn, tv);
        }
        const float alpha = __expf(m_i - mn);
        m_i = mn;
        float lsum = 0.f;
        #pragma unroll
        for (int j = 0; j < 64; j++) {
            float p = __expf(s[j] - mn);
            s[j] = p;
            lsum += p;
        }
        l_i = l_i * alpha + lsum;
        #pragma unroll
        for (int e = 0; e < 64; e++) acc[e] *= alpha;

        __syncthreads();
        #pragma unroll
        for (int j = 0; j < 64; j++) kT[j * 64 + row] = s[j];

        #pragma unroll 1
        for (int j = 0; j < 64; j++) {
            const float pj = kT[j * 64 + row];
            const float* vr = &v_s[j * 64];
            #pragma unroll
            for (int e = 0; e < 64; e += 4) {
                float4 vv = *(float4*)&vr[e];
                acc[e + 0] += pj * vv.x;
                acc[e + 1] += pj * vv.y;
                acc[e + 2] += pj * vv.z;
                acc[e + 3] += pj * vv.w;
            }
        }
    }

    const int b = bh >> 4;
    const int h = bh & 15;
    const float inv_l = 1.0f / l_i;
    float* outp = g_att + ((size_t)b * S_ + (size_t)qt * 64 + row) * D_ + h * HD_;
    #pragma unroll
    for (int e = 0; e < 64; e += 4) {
        float4 o = make_float4(acc[e] * inv_l, acc[e + 1] * inv_l,
                               acc[e + 2] * inv_l, acc[e + 3] * inv_l);
        *(float4*)(outp + e) = o;
    }
}

// ---------------------------------------------------------------------------
// Launch
// ---------------------------------------------------------------------------
extern "C" void kernel_launch(void* const* d_in, const int* in_sizes, int n_in,
                              void* d_out, int out_size)
{
    const float* x  = (const float*)d_in[0];
    const float* Wq = (const float*)d_in[1];
    const float* Wk = (const float*)d_in[2];
    const float* Wv = (const float*)d_in[3];
    const float* Wp = (const float*)d_in[4];
    const float* bp = (const float*)d_in[5];
    float* out = (float*)d_out;
    (void)in_sizes; (void)n_in; (void)out_size;

    // splits / weight repack
    const int x4 = (B_ * S_ * D_) / 4;              // 1,048,576
    split_kernel<<<(x4 + 255) / 256, 256>>>(x, 0, x4);
    convw_kernel<<<(3 * H_ * HD_ * D_) / 256, 256>>>(Wq, Wk, Wv);
    const int w4 = (D_ * D_) / 4;                   // 262,144
    split_kernel<<<(w4 + 255) / 256, 256>>>(Wp, 2, w4);

    // QKV: C[4096, 3072], 128x128 tiles
    gemm_mma<<<dim3((3 * H_ * HD_) / 128, (B_ * S_) / 128), 256>>>(0, nullptr, nullptr);

    // attention (fp32, unchanged)
    attn_kernel<<<dim3(S_ / 64, B_ * H_), 64>>>();

    // split attention output, then out projection
    split_kernel<<<(x4 + 255) / 256, 256>>>(nullptr, 1, x4);
    gemm_mma<<<dim3(D_ / 128, (B_ * S_) / 128), 256>>>(1, bp, out);
}

// round 9
// speedup vs baseline: 2.8423x; 2.8423x over previous
#include <cuda_runtime.h>
#include <cuda_bf16.h>
#include <math.h>
#include <cstdint>

// Problem constants: B=2, S=2048, D=1024, H=16, HD=64
#define B_  2
#define S_  2048
#define D_  1024
#define H_  16
#define HD_ 64
#define SCALE_ 0.03125f            // D^-0.5
#define SC2_   0.045084220f       // SCALE_ * log2(e)
#define KTOT 1024

// ---------------------------------------------------------------------------
// Scratch (device globals)
// ---------------------------------------------------------------------------
// q/k/v in bf16 hi/lo, layout [B*H][S][64]
__device__ __nv_bfloat16 g_qh[(size_t)B_*H_*S_*HD_], g_ql[(size_t)B_*H_*S_*HD_];
__device__ __nv_bfloat16 g_kh[(size_t)B_*H_*S_*HD_], g_kl[(size_t)B_*H_*S_*HD_];
__device__ __nv_bfloat16 g_vh[(size_t)B_*H_*S_*HD_], g_vl[(size_t)B_*H_*S_*HD_];
// attention output (concat heads) bf16 hi/lo, [B,S,1024]
__device__ __nv_bfloat16 g_atth[(size_t)B_*S_*D_], g_attl[(size_t)B_*S_*D_];
// input / weight splits
__device__ __nv_bfloat16 g_xh[(size_t)B_*S_*D_],  g_xl[(size_t)B_*S_*D_];
__device__ __nv_bfloat16 g_wbh[(size_t)3*H_*HD_*D_], g_wbl[(size_t)3*H_*HD_*D_];
__device__ __nv_bfloat16 g_wph[(size_t)D_*D_],    g_wpl[(size_t)D_*D_];

// ---------------------------------------------------------------------------
// PTX helpers (sm_80+ only; compile clean under compute_103)
// ---------------------------------------------------------------------------
__device__ __forceinline__ uint32_t smem_to_u32(const void* p) {
    uint32_t a;
    asm("{ .reg .u64 t; cvta.to.shared.u64 t, %1; cvt.u32.u64 %0, t; }" : "=r"(a) : "l"(p));
    return a;
}
#define LDSM4(r, addr) \
    asm volatile("ldmatrix.sync.aligned.m8n8.x4.shared.b16 {%0,%1,%2,%3}, [%4];" \
        : "=r"((r)[0]), "=r"((r)[1]), "=r"((r)[2]), "=r"((r)[3]) : "r"(addr))
#define MMA_BF16(c, a, b0, b1) \
    asm volatile("mma.sync.aligned.m16n8k16.row.col.f32.bf16.bf16.f32 " \
        "{%0,%1,%2,%3}, {%4,%5,%6,%7}, {%8,%9}, {%0,%1,%2,%3};" \
        : "+f"((c)[0]), "+f"((c)[1]), "+f"((c)[2]), "+f"((c)[3]) \
        : "r"((a)[0]), "r"((a)[1]), "r"((a)[2]), "r"((a)[3]), "r"(b0), "r"(b1))

__device__ __forceinline__ uint32_t pack_bf16(float lo, float hi) {
    __nv_bfloat162 t = __floats2bfloat162_rn(lo, hi);
    return *(uint32_t*)&t;
}
// fast exp2: rint split + deg-5 Taylor on [-0.5,0.5]; input always <= 0.
__device__ __forceinline__ float exp2f_fast(float t) {
    t = fmaxf(t, -120.f);
    int ni = __float2int_rn(t);
    float f = t - (float)ni;
    float r = 1.f + f * (0.69314718f + f * (0.24022651f + f * (0.05550411f
               + f * (0.00961812f + f * 0.00133336f))));
    return r * __int_as_float((ni + 127) << 23);
}

// ---------------------------------------------------------------------------
// Split kernels: fp32 -> bf16 hi + bf16 residual
// mode 0: x -> g_xh/g_xl     mode 2: Wp -> g_wph/g_wpl
// ---------------------------------------------------------------------------
__global__ __launch_bounds__(256) void split_kernel(const float* __restrict__ src,
                                                    int mode, int n4)
{
    int i = blockIdx.x * 256 + threadIdx.x;
    if (i >= n4) return;
    __nv_bfloat16* dh = (mode == 0) ? g_xh : g_wph;
    __nv_bfloat16* dl = (mode == 0) ? g_xl : g_wpl;

    float4 v = ((const float4*)src)[i];
    __nv_bfloat16 h0 = __float2bfloat16(v.x);
    __nv_bfloat16 h1 = __float2bfloat16(v.y);
    __nv_bfloat16 h2 = __float2bfloat16(v.z);
    __nv_bfloat16 h3 = __float2bfloat16(v.w);
    __nv_bfloat16 l0 = __float2bfloat16(v.x - __bfloat162float(h0));
    __nv_bfloat16 l1 = __float2bfloat16(v.y - __bfloat162float(h1));
    __nv_bfloat16 l2 = __float2bfloat16(v.z - __bfloat162float(h2));
    __nv_bfloat16 l3 = __float2bfloat16(v.w - __bfloat162float(h3));
    __nv_bfloat16 hs[4] = {h0, h1, h2, h3};
    __nv_bfloat16 ls[4] = {l0, l1, l2, l3};
    ((uint2*)dh)[i] = *(uint2*)hs;
    ((uint2*)dl)[i] = *(uint2*)ls;
}

// Build B matrix for QKV: rows n = which*1024 + h*64 + e, cols k (split hi/lo)
__global__ __launch_bounds__(256) void convw_kernel(const float* __restrict__ Wq,
                                                    const float* __restrict__ Wk,
                                                    const float* __restrict__ Wv)
{
    size_t idx = (size_t)blockIdx.x * 256 + threadIdx.x;
    int n = (int)(idx >> 10);
    int k = (int)(idx & 1023);
    int which = n >> 10;
    int h = (n >> 6) & 15;
    int e = n & 63;
    const float* W = (which == 0 ? Wq : which == 1 ? Wk : Wv);
    float v = W[((size_t)h * D_ + k) * HD_ + e];
    __nv_bfloat16 hi = __float2bfloat16(v);
    __nv_bfloat16 lo = __float2bfloat16(v - __bfloat162float(hi));
    g_wbh[idx] = hi;
    g_wbl[idx] = lo;
}

// ---------------------------------------------------------------------------
// Warp-MMA GEMM (bf16x3 split). mode 0: QKV (emit bf16 hi/lo q/k/v)
//                               mode 1: out-proj (A = att split, + bias, fp32)
// ---------------------------------------------------------------------------
#define SPAD 40

__global__ __launch_bounds__(256) void gemm_mma(int mode,
                                                const float* __restrict__ bias,
                                                float* __restrict__ Cout)
{
    __shared__ __nv_bfloat16 sAh[128 * SPAD], sAl[128 * SPAD];
    __shared__ __nv_bfloat16 sBh[128 * SPAD], sBl[128 * SPAD];

    const int tid  = threadIdx.x;
    const int lane = tid & 31;
    const int wid  = tid >> 5;
    const int warp_m = wid >> 2;
    const int warp_n = wid & 3;
    const int n0 = blockIdx.x * 128;
    const int m0 = blockIdx.y * 128;

    const __nv_bfloat16* Ah = mode ? g_atth : g_xh;
    const __nv_bfloat16* Al = mode ? g_attl : g_xl;
    const __nv_bfloat16* Bh = mode ? g_wph  : g_wbh;
    const __nv_bfloat16* Bl = mode ? g_wpl  : g_wbl;

    const int lrow = tid >> 1;
    const int lseg = tid & 1;
    const __nv_bfloat16* gah = Ah + (size_t)(m0 + lrow) * KTOT + lseg * 16;
    const __nv_bfloat16* gal = Al + (size_t)(m0 + lrow) * KTOT + lseg * 16;
    const __nv_bfloat16* gbh = Bh + (size_t)(n0 + lrow) * KTOT + lseg * 16;
    const __nv_bfloat16* gbl = Bl + (size_t)(n0 + lrow) * KTOT + lseg * 16;

    const uint32_t uAh = smem_to_u32(sAh), uAl = smem_to_u32(sAl);
    const uint32_t uBh = smem_to_u32(sBh), uBl = smem_to_u32(sBl);

    const int lrm = lane & 15;
    const int lck = (lane >> 4) * 8;

    float acc[4][4][4];
    #pragma unroll
    for (int i = 0; i < 4; i++)
        #pragma unroll
        for (int j = 0; j < 4; j++)
            #pragma unroll
            for (int r = 0; r < 4; r++) acc[i][j][r] = 0.f;

    const int sbase = lrow * SPAD + lseg * 16;

    for (int kc = 0; kc < KTOT / 32; kc++) {
        #pragma unroll
        for (int c = 0; c < 2; c++) {
            *(uint4*)&sAh[sbase + c * 8] = ((const uint4*)gah)[c];
            *(uint4*)&sAl[sbase + c * 8] = ((const uint4*)gal)[c];
            *(uint4*)&sBh[sbase + c * 8] = ((const uint4*)gbh)[c];
            *(uint4*)&sBl[sbase + c * 8] = ((const uint4*)gbl)[c];
        }
        __syncthreads();

        #pragma unroll
        for (int ks = 0; ks < 2; ks++) {
            const int koff = ks * 16 + lck;
            uint32_t afh[4][4], afl[4][4];
            uint32_t bfh[2][4], bfl[2][4];
            #pragma unroll
            for (int mt = 0; mt < 4; mt++) {
                const uint32_t off = 2u * ((warp_m * 64 + mt * 16 + lrm) * SPAD + koff);
                LDSM4(afh[mt], uAh + off);
                LDSM4(afl[mt], uAl + off);
            }
            #pragma unroll
            for (int np = 0; np < 2; np++) {
                const uint32_t off = 2u * ((warp_n * 32 + np * 16 + lrm) * SPAD + koff);
                LDSM4(bfh[np], uBh + off);
                LDSM4(bfl[np], uBl + off);
            }
            #pragma unroll
            for (int mt = 0; mt < 4; mt++) {
                #pragma unroll
                for (int nt = 0; nt < 4; nt++) {
                    const int np = nt >> 1, sel = nt & 1;
                    MMA_BF16(acc[mt][nt], afh[mt], bfh[np][sel], bfh[np][sel + 2]);
                    MMA_BF16(acc[mt][nt], afh[mt], bfl[np][sel], bfl[np][sel + 2]);
                    MMA_BF16(acc[mt][nt], afl[mt], bfh[np][sel], bfh[np][sel + 2]);
                }
            }
        }
        __syncthreads();
        gah += 32; gal += 32; gbh += 32; gbl += 32;
    }

    // ------------------------------ epilogue ------------------------------
    #pragma unroll
    for (int mt = 0; mt < 4; mt++) {
        #pragma unroll
        for (int nt = 0; nt < 4; nt++) {
            const int mrow = m0 + warp_m * 64 + mt * 16 + (lane >> 2);
            const int ncol = n0 + warp_n * 32 + nt * 8 + (lane & 3) * 2;
            if (mode == 1) {
                const float b0 = bias[ncol], b1 = bias[ncol + 1];
                float2 v0 = make_float2(acc[mt][nt][0] + b0, acc[mt][nt][1] + b1);
                float2 v1 = make_float2(acc[mt][nt][2] + b0, acc[mt][nt][3] + b1);
                *(float2*)(Cout + (size_t)mrow * D_ + ncol)       = v0;
                *(float2*)(Cout + (size_t)(mrow + 8) * D_ + ncol) = v1;
            } else {
                const int which = ncol >> 10;
                const int h = (ncol >> 6) & 15;
                const int e = ncol & 63;
                __nv_bfloat16* bhp = (which == 0 ? g_qh : which == 1 ? g_kh : g_vh);
                __nv_bfloat16* blp = (which == 0 ? g_ql : which == 1 ? g_kl : g_vl);
                #pragma unroll
                for (int half = 0; half < 2; half++) {
                    const int mr = mrow + half * 8;
                    const float a0 = acc[mt][nt][half * 2 + 0];
                    const float a1 = acc[mt][nt][half * 2 + 1];
                    const int b = mr >> 11, s = mr & 2047;
                    const size_t base = (((size_t)(b * H_ + h) * S_) + s) * HD_ + e;
                    __nv_bfloat16 h0 = __float2bfloat16(a0);
                    __nv_bfloat16 h1 = __float2bfloat16(a1);
                    *(uint32_t*)&bhp[base] = pack_bf16(__bfloat162float(h0) * 0.f + a0,  a1);
                    // NOTE: pack hi parts properly (see below) — overwritten next line
                    *(uint32_t*)&bhp[base] = pack_bf16(a0, a1);
                    *(uint32_t*)&blp[base] = pack_bf16(a0 - __bfloat162float(h0),
                                                       a1 - __bfloat162float(h1));
                }
            }
        }
    }
}

// ---------------------------------------------------------------------------
// MMA flash attention. Block = 128 q rows of one (b,h). 256 threads / 8 warps.
// Warp w owns q-rows [w*16, w*16+16). KV tiles of 128.
// QK: A=Q (hi/lo frags preloaded), B=K rows (non-trans ldsm, proven pattern).
// PV: A=P frags straight from S accumulators, B=V transposed in smem.
// Softmax in base-2 with polynomial exp2 (no MUFU).
// ---------------------------------------------------------------------------
#define QK_PAD 72       // stride for 64-col tiles (elems)
#define VT_PAD 136      // stride for 128-col Vt tiles (elems)
#define SM_K_H   0
#define SM_K_L   (128 * QK_PAD)
#define SM_VT_H  (2 * 128 * QK_PAD)
#define SM_VT_L  (2 * 128 * QK_PAD + 64 * VT_PAD)
#define ATT_SMEM ((2 * 128 * QK_PAD + 2 * 64 * VT_PAD) * 2)

__global__ __launch_bounds__(256) void attn_mma_kernel()
{
    extern __shared__ __nv_bfloat16 sm[];
    const int qt  = (int)gridDim.x - 1 - (int)blockIdx.x;   // heavy blocks first
    const int bh  = blockIdx.y;
    const int tid = threadIdx.x;
    const int lane = tid & 31;
    const int wid  = tid >> 5;
    const int m0g = qt * 128;

    const __nv_bfloat16* Qh = g_qh + (size_t)bh * S_ * HD_;
    const __nv_bfloat16* Ql = g_ql + (size_t)bh * S_ * HD_;
    const __nv_bfloat16* Kh = g_kh + (size_t)bh * S_ * HD_;
    const __nv_bfloat16* Kl = g_kl + (size_t)bh * S_ * HD_;
    const __nv_bfloat16* Vh = g_vh + (size_t)bh * S_ * HD_;
    const __nv_bfloat16* Vl = g_vl + (size_t)bh * S_ * HD_;

    const uint32_t uK  = smem_to_u32(sm);               // K/Q buffer (hi at 0, lo at SM_K_L)
    const uint32_t uVt = smem_to_u32(sm + SM_VT_H);

    const int lrow = tid >> 1;          // 0..127
    const int lseg = tid & 1;
    const int lrm  = lane & 15;
    const int lck  = (lane >> 4) * 8;

    // ---- stage Q into K-buffer, build Q fragments ----
    {
        const uint4* qh4 = (const uint4*)(Qh + (size_t)(m0g + lrow) * HD_ + lseg * 32);
        const uint4* ql4 = (const uint4*)(Ql + (size_t)(m0g + lrow) * HD_ + lseg * 32);
        uint4* dsth = (uint4*)&sm[SM_K_H + lrow * QK_PAD + lseg * 32];
        uint4* dstl = (uint4*)&sm[SM_K_L + lrow * QK_PAD + lseg * 32];
        #pragma unroll
        for (int c = 0; c < 4; c++) { dsth[c] = qh4[c]; dstl[c] = ql4[c]; }
    }
    __syncthreads();
    uint32_t aQh[4][4], aQl[4][4];
    #pragma unroll
    for (int dk = 0; dk < 4; dk++) {
        const uint32_t off = 2u * ((wid * 16 + lrm) * QK_PAD + dk * 16 + lck);
        LDSM4(aQh[dk], uK + 2u * SM_K_H + off);
        LDSM4(aQl[dk], uK + 2u * SM_K_L + off);
    }

    // ---- state ----
    float accO[8][4];
    #pragma unroll
    for (int i = 0; i < 8; i++)
        #pragma unroll
        for (int r = 0; r < 4; r++) accO[i][r] = 0.f;
    float m0s = -1e30f, m1s = -1e30f, l0s = 0.f, l1s = 0.f;

    const int r0g = m0g + wid * 16 + (lane >> 2);
    const int r1g = r0g + 8;
    const int ntiles = qt + 1;

    for (int kt = 0; kt < ntiles; kt++) {
        const int j0 = kt * 128;
        __syncthreads();   // previous ldsm reads (and Q frag reads) complete

        // ---- load K tile (hi/lo) ----
        {
            const uint4* kh4 = (const uint4*)(Kh + (size_t)(j0 + lrow) * HD_ + lseg * 32);
            const uint4* kl4 = (const uint4*)(Kl + (size_t)(j0 + lrow) * HD_ + lseg * 32);
            uint4* dsth = (uint4*)&sm[SM_K_H + lrow * QK_PAD + lseg * 32];
            uint4* dstl = (uint4*)&sm[SM_K_L + lrow * QK_PAD + lseg * 32];
            #pragma unroll
            for (int c = 0; c < 4; c++) { dsth[c] = kh4[c]; dstl[c] = kl4[c]; }
        }
        // ---- load V tile transposed: sVt[e][j] ----
        {
            const __nv_bfloat16* vrh = Vh + (size_t)(j0 + lrow) * HD_;
            const __nv_bfloat16* vrl = Vl + (size_t)(j0 + lrow) * HD_;
            #pragma unroll
            for (int c = 0; c < 4; c++) {
                const int e0 = lseg * 32 + c * 8;
                uint4 vh4 = *(const uint4*)(vrh + e0);
                uint4 vl4 = *(const uint4*)(vrl + e0);
                const __nv_bfloat16* eh = (const __nv_bfloat16*)&vh4;
                const __nv_bfloat16* el = (const __nv_bfloat16*)&vl4;
                #pragma unroll
                for (int i = 0; i < 8; i++) {
                    sm[SM_VT_H + (e0 + i) * VT_PAD + lrow] = eh[i];
                    sm[SM_VT_L + (e0 + i) * VT_PAD + lrow] = el[i];
                }
            }
        }
        __syncthreads();

        // ---- QK: S[16 x 128] per warp ----
        float accS[16][4];
        #pragma unroll
        for (int i = 0; i < 16; i++)
            #pragma unroll
            for (int r = 0; r < 4; r++) accS[i][r] = 0.f;

        #pragma unroll
        for (int dk = 0; dk < 4; dk++) {
            #pragma unroll
            for (int jc = 0; jc < 8; jc++) {
                uint32_t kh[4], kl[4];
                const uint32_t off = 2u * ((jc * 16 + lrm) * QK_PAD + dk * 16 + lck);
                LDSM4(kh, uK + 2u * SM_K_H + off);
                LDSM4(kl, uK + 2u * SM_K_L + off);
                MMA_BF16(accS[2*jc],   aQh[dk], kh[0], kh[2]);
                MMA_BF16(accS[2*jc+1], aQh[dk], kh[1], kh[3]);
                MMA_BF16(accS[2*jc],   aQh[dk], kl[0], kl[2]);
                MMA_BF16(accS[2*jc+1], aQh[dk], kl[1], kl[3]);
                MMA_BF16(accS[2*jc],   aQl[dk], kh[0], kh[2]);
                MMA_BF16(accS[2*jc+1], aQl[dk], kh[1], kh[3]);
            }
        }

        // ---- softmax (base-2) ----
        const bool diag = (kt == qt);
        float mx0 = -1e30f, mx1 = -1e30f;
        #pragma unroll
        for (int nt = 0; nt < 16; nt++) {
            const int jb = j0 + nt * 8 + (lane & 3) * 2;
            float c0 = accS[nt][0] * SC2_;
            float c1 = accS[nt][1] * SC2_;
            float c2 = accS[nt][2] * SC2_;
            float c3 = accS[nt][3] * SC2_;
            if (diag) {
                if (jb     > r0g) c0 = -1e30f;
                if (jb + 1 > r0g) c1 = -1e30f;
                if (jb     > r1g) c2 = -1e30f;
                if (jb + 1 > r1g) c3 = -1e30f;
            }
            accS[nt][0] = c0; accS[nt][1] = c1; accS[nt][2] = c2; accS[nt][3] = c3;
            mx0 = fmaxf(mx0, fmaxf(c0, c1));
            mx1 = fmaxf(mx1, fmaxf(c2, c3));
        }
        mx0 = fmaxf(mx0, __shfl_xor_sync(0xffffffffu, mx0, 1));
        mx0 = fmaxf(mx0, __shfl_xor_sync(0xffffffffu, mx0, 2));
        mx1 = fmaxf(mx1, __shfl_xor_sync(0xffffffffu, mx1, 1));
        mx1 = fmaxf(mx1, __shfl_xor_sync(0xffffffffu, mx1, 2));

        const float mn0 = fmaxf(m0s, mx0);
        const float mn1 = fmaxf(m1s, mx1);
        const float al0 = exp2f_fast(m0s - mn0);
        const float al1 = exp2f_fast(m1s - mn1);
        m0s = mn0; m1s = mn1;

        float ls0 = 0.f, ls1 = 0.f;
        #pragma unroll
        for (int nt = 0; nt < 16; nt++) {
            float p0 = exp2f_fast(accS[nt][0] - mn0);
            float p1 = exp2f_fast(accS[nt][1] - mn0);
            float p2 = exp2f_fast(accS[nt][2] - mn1);
            float p3 = exp2f_fast(accS[nt][3] - mn1);
            accS[nt][0] = p0; accS[nt][1] = p1; accS[nt][2] = p2; accS[nt][3] = p3;
            ls0 += p0 + p1;
            ls1 += p2 + p3;
        }
        ls0 += __shfl_xor_sync(0xffffffffu, ls0, 1);
        ls0 += __shfl_xor_sync(0xffffffffu, ls0, 2);
        ls1 += __shfl_xor_sync(0xffffffffu, ls1, 1);
        ls1 += __shfl_xor_sync(0xffffffffu, ls1, 2);
        l0s = l0s * al0 + ls0;
        l1s = l1s * al1 + ls1;

        #pragma unroll
        for (int i = 0; i < 8; i++) {
            accO[i][0] *= al0; accO[i][1] *= al0;
            accO[i][2] *= al1; accO[i][3] *= al1;
        }

        // ---- PV: accO += P @ Vt^T (A-frags from accS, 3-pass split) ----
        #pragma unroll
        for (int kt2 = 0; kt2 < 8; kt2++) {
            uint32_t aPh[4], aPl[4];
            {
                const float p00 = accS[2*kt2][0],   p01 = accS[2*kt2][1];
                const float p02 = accS[2*kt2][2],   p03 = accS[2*kt2][3];
                const float p10 = accS[2*kt2+1][0], p11 = accS[2*kt2+1][1];
                const float p12 = accS[2*kt2+1][2], p13 = accS[2*kt2+1][3];
                aPh[0] = pack_bf16(p00, p01);
                aPh[1] = pack_bf16(p02, p03);
                aPh[2] = pack_bf16(p10, p11);
                aPh[3] = pack_bf16(p12, p13);
                aPl[0] = pack_bf16(p00 - __bfloat162float(__float2bfloat16(p00)),
                                   p01 - __bfloat162float(__float2bfloat16(p01)));
                aPl[1] = pack_bf16(p02 - __bfloat162float(__float2bfloat16(p02)),
                                   p03 - __bfloat162float(__float2bfloat16(p03)));
                aPl[2] = pack_bf16(p10 - __bfloat162float(__float2bfloat16(p10)),
                                   p11 - __bfloat162float(__float2bfloat16(p11)));
                aPl[3] = pack_bf16(p12 - __bfloat162float(__float2bfloat16(p12)),
                                   p13 - __bfloat162float(__float2bfloat16(p13)));
            }
            #pragma unroll
            for (int ec = 0; ec < 2; ec++) {
                uint32_t vh[4], vl[4];
                const uint32_t off = 2u * ((ec * 16 + lrm) * VT_PAD + kt2 * 16 + lck);
                LDSM4(vh, uVt + off);
                LDSM4(vl, uVt + 2u * (64 * VT_PAD) + off);
                MMA_BF16(accO[2*ec],   aPh, vh[0], vh[2]);
                MMA_BF16(accO[2*ec+1], aPh, vh[1], vh[3]);
                MMA_BF16(accO[2*ec],   aPh, vl[0], vl[2]);
                MMA_BF16(accO[2*ec+1], aPh, vl[1], vl[3]);
                MMA_BF16(accO[2*ec],   aPl, vh[0], vh[2]);
                MMA_BF16(accO[2*ec+1], aPl, vh[1], vh[3]);
            }
            #pragma unroll
            for (int ec = 2; ec < 4; ec++) {
                uint32_t vh[4], vl[4];
                const uint32_t off = 2u * ((ec * 16 + lrm) * VT_PAD + kt2 * 16 + lck);
                LDSM4(vh, uVt + off);
                LDSM4(vl, uVt + 2u * (64 * VT_PAD) + off);
                MMA_BF16(accO[2*ec],   aPh, vh[0], vh[2]);
                MMA_BF16(accO[2*ec+1], aPh, vh[1], vh[3]);
                MMA_BF16(accO[2*ec],   aPh, vl[0], vl[2]);
                MMA_BF16(accO[2*ec+1], aPh, vl[1], vl[3]);
                MMA_BF16(accO[2*ec],   aPl, vh[0], vh[2]);
                MMA_BF16(accO[2*ec+1], aPl, vh[1], vh[3]);
            }
        }
    }

    // ---- epilogue: normalize, split hi/lo, write concat layout ----
    const int b = bh >> 4;
    const int h = bh & 15;
    const float inv0 = 1.f / l0s;
    const float inv1 = 1.f / l1s;
    #pragma unroll
    for (int nt = 0; nt < 8; nt++) {
        const int e = nt * 8 + (lane & 3) * 2;
        #pragma unroll
        for (int half = 0; half < 2; half++) {
            const int s = (half == 0) ? (r0g) : (r1g);
            const float sc = (half == 0) ? inv0 : inv1;
            const float a0 = accO[nt][half * 2 + 0] * sc;
            const float a1 = accO[nt][half * 2 + 1] * sc;
            const size_t base = ((size_t)b * S_ + s) * D_ + h * HD_ + e;
            __nv_bfloat16 h0 = __float2bfloat16(a0);
            __nv_bfloat16 h1 = __float2bfloat16(a1);
            *(uint32_t*)&g_atth[base] = pack_bf16(a0, a1);
            *(uint32_t*)&g_attl[base] = pack_bf16(a0 - __bfloat162float(h0),
                                                  a1 - __bfloat162float(h1));
        }
    }
}

// ---------------------------------------------------------------------------
// Launch
// ---------------------------------------------------------------------------
extern "C" void kernel_launch(void* const* d_in, const int* in_sizes, int n_in,
                              void* d_out, int out_size)
{
    const float* x  = (const float*)d_in[0];
    const float* Wq = (const float*)d_in[1];
    const float* Wk = (const float*)d_in[2];
    const float* Wv = (const float*)d_in[3];
    const float* Wp = (const float*)d_in[4];
    const float* bp = (const float*)d_in[5];
    float* out = (float*)d_out;
    (void)in_sizes; (void)n_in; (void)out_size;

    cudaFuncSetAttribute(attn_mma_kernel,
                         cudaFuncAttributeMaxDynamicSharedMemorySize, ATT_SMEM);

    const int x4 = (B_ * S_ * D_) / 4;
    split_kernel<<<(x4 + 255) / 256, 256>>>(x, 0, x4);
    convw_kernel<<<(3 * H_ * HD_ * D_) / 256, 256>>>(Wq, Wk, Wv);
    const int w4 = (D_ * D_) / 4;
    split_kernel<<<(w4 + 255) / 256, 256>>>(Wp, 2, w4);

    // QKV: C[4096, 3072], 128x128 tiles -> bf16 hi/lo q/k/v
    gemm_mma<<<dim3((3 * H_ * HD_) / 128, (B_ * S_) / 128), 256>>>(0, nullptr, nullptr);

    // MMA flash attention -> g_atth/g_attl
    attn_mma_kernel<<<dim3(S_ / 128, B_ * H_), 256, ATT_SMEM>>>();

    // out projection
    gemm_mma<<<dim3(D_ / 128, (B_ * S_) / 128), 256>>>(1, bp, out);
}

// round 10
// speedup vs baseline: 3.1509x; 1.1086x over previous
#include <cuda_runtime.h>
#include <cuda_bf16.h>
#include <math.h>
#include <cstdint>

// Problem constants: B=2, S=2048, D=1024, H=16, HD=64
#define B_  2
#define S_  2048
#define D_  1024
#define H_  16
#define HD_ 64
#define SC2_   0.045084220f       // D^-0.5 * log2(e)
#define KTOT 1024

// ---------------------------------------------------------------------------
// Scratch (device globals)
// ---------------------------------------------------------------------------
__device__ __nv_bfloat16 g_qh[(size_t)B_*H_*S_*HD_], g_ql[(size_t)B_*H_*S_*HD_];
__device__ __nv_bfloat16 g_kh[(size_t)B_*H_*S_*HD_], g_kl[(size_t)B_*H_*S_*HD_];
__device__ __nv_bfloat16 g_vh[(size_t)B_*H_*S_*HD_], g_vl[(size_t)B_*H_*S_*HD_];
__device__ __nv_bfloat16 g_atth[(size_t)B_*S_*D_], g_attl[(size_t)B_*S_*D_];
__device__ __nv_bfloat16 g_xh[(size_t)B_*S_*D_],  g_xl[(size_t)B_*S_*D_];
__device__ __nv_bfloat16 g_wbh[(size_t)3*H_*HD_*D_], g_wbl[(size_t)3*H_*HD_*D_];
__device__ __nv_bfloat16 g_wph[(size_t)D_*D_],    g_wpl[(size_t)D_*D_];

// ---------------------------------------------------------------------------
// PTX helpers (sm_80+ only; compile clean under compute_103)
// ---------------------------------------------------------------------------
__device__ __forceinline__ uint32_t smem_to_u32(const void* p) {
    uint32_t a;
    asm("{ .reg .u64 t; cvta.to.shared.u64 t, %1; cvt.u32.u64 %0, t; }" : "=r"(a) : "l"(p));
    return a;
}
#define LDSM4(r, addr) \
    asm volatile("ldmatrix.sync.aligned.m8n8.x4.shared.b16 {%0,%1,%2,%3}, [%4];" \
        : "=r"((r)[0]), "=r"((r)[1]), "=r"((r)[2]), "=r"((r)[3]) : "r"(addr))
#define LDSM4T(r, addr) \
    asm volatile("ldmatrix.sync.aligned.m8n8.x4.trans.shared.b16 {%0,%1,%2,%3}, [%4];" \
        : "=r"((r)[0]), "=r"((r)[1]), "=r"((r)[2]), "=r"((r)[3]) : "r"(addr))
#define MMA_BF16(c, a, b0, b1) \
    asm volatile("mma.sync.aligned.m16n8k16.row.col.f32.bf16.bf16.f32 " \
        "{%0,%1,%2,%3}, {%4,%5,%6,%7}, {%8,%9}, {%0,%1,%2,%3};" \
        : "+f"((c)[0]), "+f"((c)[1]), "+f"((c)[2]), "+f"((c)[3]) \
        : "r"((a)[0]), "r"((a)[1]), "r"((a)[2]), "r"((a)[3]), "r"(b0), "r"(b1))
#define CP16(saddr, gptr) \
    asm volatile("cp.async.cg.shared.global [%0], [%1], 16;" \
        :: "r"((uint32_t)(saddr)), "l"(gptr))
#define CP_COMMIT() asm volatile("cp.async.commit_group;" ::: "memory")
#define CP_WAIT(n)  asm volatile("cp.async.wait_group %0;" :: "n"(n) : "memory")

__device__ __forceinline__ uint32_t pack_bf16(float lo, float hi) {
    __nv_bfloat162 t = __floats2bfloat162_rn(lo, hi);
    return *(uint32_t*)&t;
}
// fast exp2: rint split + deg-5 poly; input always <= 0.
__device__ __forceinline__ float exp2f_fast(float t) {
    t = fmaxf(t, -120.f);
    int ni = __float2int_rn(t);
    float f = t - (float)ni;
    float r = 1.f + f * (0.69314718f + f * (0.24022651f + f * (0.05550411f
               + f * (0.00961812f + f * 0.00133336f))));
    return r * __int_as_float((ni + 127) << 23);
}

// ---------------------------------------------------------------------------
// Split kernels: fp32 -> bf16 hi + bf16 residual
// ---------------------------------------------------------------------------
__global__ __launch_bounds__(256) void split_kernel(const float* __restrict__ src,
                                                    int mode, int n4)
{
    int i = blockIdx.x * 256 + threadIdx.x;
    if (i >= n4) return;
    __nv_bfloat16* dh = (mode == 0) ? g_xh : g_wph;
    __nv_bfloat16* dl = (mode == 0) ? g_xl : g_wpl;

    float4 v = ((const float4*)src)[i];
    __nv_bfloat16 h0 = __float2bfloat16(v.x);
    __nv_bfloat16 h1 = __float2bfloat16(v.y);
    __nv_bfloat16 h2 = __float2bfloat16(v.z);
    __nv_bfloat16 h3 = __float2bfloat16(v.w);
    __nv_bfloat16 l0 = __float2bfloat16(v.x - __bfloat162float(h0));
    __nv_bfloat16 l1 = __float2bfloat16(v.y - __bfloat162float(h1));
    __nv_bfloat16 l2 = __float2bfloat16(v.z - __bfloat162float(h2));
    __nv_bfloat16 l3 = __float2bfloat16(v.w - __bfloat162float(h3));
    __nv_bfloat16 hs[4] = {h0, h1, h2, h3};
    __nv_bfloat16 ls[4] = {l0, l1, l2, l3};
    ((uint2*)dh)[i] = *(uint2*)hs;
    ((uint2*)dl)[i] = *(uint2*)ls;
}

__global__ __launch_bounds__(256) void convw_kernel(const float* __restrict__ Wq,
                                                    const float* __restrict__ Wk,
                                                    const float* __restrict__ Wv)
{
    size_t idx = (size_t)blockIdx.x * 256 + threadIdx.x;
    int n = (int)(idx >> 10);
    int k = (int)(idx & 1023);
    int which = n >> 10;
    int h = (n >> 6) & 15;
    int e = n & 63;
    const float* W = (which == 0 ? Wq : which == 1 ? Wk : Wv);
    float v = W[((size_t)h * D_ + k) * HD_ + e];
    __nv_bfloat16 hi = __float2bfloat16(v);
    __nv_bfloat16 lo = __float2bfloat16(v - __bfloat162float(hi));
    g_wbh[idx] = hi;
    g_wbl[idx] = lo;
}

// ---------------------------------------------------------------------------
// Warp-MMA GEMM, bf16x3 split, cp.async 2-stage pipeline.
// mode 0: QKV (emit bf16 hi/lo q/k/v)   mode 1: out-proj (+bias, fp32 out)
// ---------------------------------------------------------------------------
#define SPAD 40
#define ST_AH 0
#define ST_AL (128 * SPAD)
#define ST_BH (2 * 128 * SPAD)
#define ST_BL (3 * 128 * SPAD)
#define STAGE_BYTES (4 * 128 * SPAD * 2)       // 40960
#define GEMM_SMEM   (2 * STAGE_BYTES)          // 81920

__global__ __launch_bounds__(256, 2) void gemm_mma(int mode,
                                                   const float* __restrict__ bias,
                                                   float* __restrict__ Cout)
{
    extern __shared__ __nv_bfloat16 dsm[];
    const uint32_t ub = smem_to_u32(dsm);

    const int tid  = threadIdx.x;
    const int lane = tid & 31;
    const int wid  = tid >> 5;
    const int warp_m = wid >> 2;
    const int warp_n = wid & 3;
    const int n0 = blockIdx.x * 128;
    const int m0 = blockIdx.y * 128;

    const __nv_bfloat16* Ah = mode ? g_atth : g_xh;
    const __nv_bfloat16* Al = mode ? g_attl : g_xl;
    const __nv_bfloat16* Bh = mode ? g_wph  : g_wbh;
    const __nv_bfloat16* Bl = mode ? g_wpl  : g_wbl;

    const int lrow = tid >> 1;
    const int lseg = tid & 1;
    const __nv_bfloat16* ga_h = Ah + (size_t)(m0 + lrow) * KTOT + lseg * 16;
    const __nv_bfloat16* ga_l = Al + (size_t)(m0 + lrow) * KTOT + lseg * 16;
    const __nv_bfloat16* gb_h = Bh + (size_t)(n0 + lrow) * KTOT + lseg * 16;
    const __nv_bfloat16* gb_l = Bl + (size_t)(n0 + lrow) * KTOT + lseg * 16;
    const uint32_t sbo = 2u * (lrow * SPAD + lseg * 16);   // byte offset in tile

    const int lrm = lane & 15;
    const int lck = (lane >> 4) * 8;

    float acc[4][4][4];
    #pragma unroll
    for (int i = 0; i < 4; i++)
        #pragma unroll
        for (int j = 0; j < 4; j++)
            #pragma unroll
            for (int r = 0; r < 4; r++) acc[i][j][r] = 0.f;

    // ---- prologue: stage 0 ----
    {
        const uint32_t sb = ub + sbo;
        CP16(sb + 2*ST_AH,      ga_h);      CP16(sb + 2*ST_AH + 16, ga_h + 8);
        CP16(sb + 2*ST_AL,      ga_l);      CP16(sb + 2*ST_AL + 16, ga_l + 8);
        CP16(sb + 2*ST_BH,      gb_h);      CP16(sb + 2*ST_BH + 16, gb_h + 8);
        CP16(sb + 2*ST_BL,      gb_l);      CP16(sb + 2*ST_BL + 16, gb_l + 8);
    }
    CP_COMMIT();

    const int NKC = KTOT / 32;
    for (int kc = 0; kc < NKC; kc++) {
        // issue next stage
        if (kc + 1 < NKC) {
            const int k1 = (kc + 1) * 32;
            const uint32_t sb = ub + ((kc + 1) & 1) * STAGE_BYTES + sbo;
            CP16(sb + 2*ST_AH,      ga_h + k1);      CP16(sb + 2*ST_AH + 16, ga_h + k1 + 8);
            CP16(sb + 2*ST_AL,      ga_l + k1);      CP16(sb + 2*ST_AL + 16, ga_l + k1 + 8);
            CP16(sb + 2*ST_BH,      gb_h + k1);      CP16(sb + 2*ST_BH + 16, gb_h + k1 + 8);
            CP16(sb + 2*ST_BL,      gb_l + k1);      CP16(sb + 2*ST_BL + 16, gb_l + k1 + 8);
        }
        CP_COMMIT();
        CP_WAIT(1);
        __syncthreads();

        const uint32_t us = ub + (kc & 1) * STAGE_BYTES;
        #pragma unroll
        for (int ks = 0; ks < 2; ks++) {
            const int koff = ks * 16 + lck;
            uint32_t afh[4][4], afl[4][4];
            uint32_t bfh[2][4], bfl[2][4];
            #pragma unroll
            for (int mt = 0; mt < 4; mt++) {
                const uint32_t off = 2u * ((warp_m * 64 + mt * 16 + lrm) * SPAD + koff);
                LDSM4(afh[mt], us + 2*ST_AH + off);
                LDSM4(afl[mt], us + 2*ST_AL + off);
            }
            #pragma unroll
            for (int np = 0; np < 2; np++) {
                const uint32_t off = 2u * ((warp_n * 32 + np * 16 + lrm) * SPAD + koff);
                LDSM4(bfh[np], us + 2*ST_BH + off);
                LDSM4(bfl[np], us + 2*ST_BL + off);
            }
            #pragma unroll
            for (int mt = 0; mt < 4; mt++) {
                #pragma unroll
                for (int nt = 0; nt < 4; nt++) {
                    const int np = nt >> 1, sel = nt & 1;
                    MMA_BF16(acc[mt][nt], afh[mt], bfh[np][sel], bfh[np][sel + 2]);
                    MMA_BF16(acc[mt][nt], afh[mt], bfl[np][sel], bfl[np][sel + 2]);
                    MMA_BF16(acc[mt][nt], afl[mt], bfh[np][sel], bfh[np][sel + 2]);
                }
            }
        }
        __syncthreads();
    }

    // ------------------------------ epilogue ------------------------------
    #pragma unroll
    for (int mt = 0; mt < 4; mt++) {
        #pragma unroll
        for (int nt = 0; nt < 4; nt++) {
            const int mrow = m0 + warp_m * 64 + mt * 16 + (lane >> 2);
            const int ncol = n0 + warp_n * 32 + nt * 8 + (lane & 3) * 2;
            if (mode == 1) {
                const float b0 = bias[ncol], b1 = bias[ncol + 1];
                float2 v0 = make_float2(acc[mt][nt][0] + b0, acc[mt][nt][1] + b1);
                float2 v1 = make_float2(acc[mt][nt][2] + b0, acc[mt][nt][3] + b1);
                *(float2*)(Cout + (size_t)mrow * D_ + ncol)       = v0;
                *(float2*)(Cout + (size_t)(mrow + 8) * D_ + ncol) = v1;
            } else {
                const int which = ncol >> 10;
                const int h = (ncol >> 6) & 15;
                const int e = ncol & 63;
                __nv_bfloat16* bhp = (which == 0 ? g_qh : which == 1 ? g_kh : g_vh);
                __nv_bfloat16* blp = (which == 0 ? g_ql : which == 1 ? g_kl : g_vl);
                #pragma unroll
                for (int half = 0; half < 2; half++) {
                    const int mr = mrow + half * 8;
                    const float a0 = acc[mt][nt][half * 2 + 0];
                    const float a1 = acc[mt][nt][half * 2 + 1];
                    const int b = mr >> 11, s = mr & 2047;
                    const size_t base = (((size_t)(b * H_ + h) * S_) + s) * HD_ + e;
                    const float h0f = __bfloat162float(__float2bfloat16(a0));
                    const float h1f = __bfloat162float(__float2bfloat16(a1));
                    *(uint32_t*)&bhp[base] = pack_bf16(a0, a1);
                    *(uint32_t*)&blp[base] = pack_bf16(a0 - h0f, a1 - h1f);
                }
            }
        }
    }
}

// ---------------------------------------------------------------------------
// MMA flash attention. Block = 128 q rows of one (b,h). 256 threads / 8 warps.
// K row-major (QK via non-trans ldsm), V row-major (PV via trans ldsm).
// cp.async split groups: K waited before QK, V waited after softmax.
// ---------------------------------------------------------------------------
#define APAD 72
#define AK_H 0
#define AK_L (128 * APAD)
#define AV_H (2 * 128 * APAD)
#define AV_L (3 * 128 * APAD)
#define ATT_SMEM (4 * 128 * APAD * 2)          // 73728 bytes

__global__ __launch_bounds__(256) void attn_mma_kernel()
{
    extern __shared__ __nv_bfloat16 sm[];
    const uint32_t uS = smem_to_u32(sm);
    const int qt  = (int)gridDim.x - 1 - (int)blockIdx.x;   // heavy blocks first
    const int bh  = blockIdx.y;
    const int tid = threadIdx.x;
    const int lane = tid & 31;
    const int wid  = tid >> 5;
    const int m0g = qt * 128;

    const __nv_bfloat16* Qh = g_qh + (size_t)bh * S_ * HD_;
    const __nv_bfloat16* Ql = g_ql + (size_t)bh * S_ * HD_;
    const __nv_bfloat16* Kh = g_kh + (size_t)bh * S_ * HD_;
    const __nv_bfloat16* Kl = g_kl + (size_t)bh * S_ * HD_;
    const __nv_bfloat16* Vh = g_vh + (size_t)bh * S_ * HD_;
    const __nv_bfloat16* Vl = g_vl + (size_t)bh * S_ * HD_;

    const int lrow = tid >> 1;          // 0..127
    const int lseg = tid & 1;
    const int lrm  = lane & 15;
    const int lck  = (lane >> 4) * 8;
    const uint32_t rowb = 2u * (lrow * APAD + lseg * 32);   // byte offset of half-row

    // ---- stage Q into K-buffer via cp.async, build Q fragments ----
    {
        const __nv_bfloat16* q_h = Qh + (size_t)(m0g + lrow) * HD_ + lseg * 32;
        const __nv_bfloat16* q_l = Ql + (size_t)(m0g + lrow) * HD_ + lseg * 32;
        #pragma unroll
        for (int c = 0; c < 4; c++) {
            CP16(uS + 2*AK_H + rowb + c * 16, q_h + c * 8);
            CP16(uS + 2*AK_L + rowb + c * 16, q_l + c * 8);
        }
        CP_COMMIT();
        CP_WAIT(0);
        __syncthreads();
    }
    uint32_t aQh[4][4], aQl[4][4];
    #pragma unroll
    for (int dk = 0; dk < 4; dk++) {
        const uint32_t off = 2u * ((wid * 16 + lrm) * APAD + dk * 16 + lck);
        LDSM4(aQh[dk], uS + 2*AK_H + off);
        LDSM4(aQl[dk], uS + 2*AK_L + off);
    }

    float accO[8][4];
    #pragma unroll
    for (int i = 0; i < 8; i++)
        #pragma unroll
        for (int r = 0; r < 4; r++) accO[i][r] = 0.f;
    float m0s = -1e30f, m1s = -1e30f, l0s = 0.f, l1s = 0.f;

    const int r0g = m0g + wid * 16 + (lane >> 2);
    const int r1g = r0g + 8;
    const int ntiles = qt + 1;

    for (int kt = 0; kt < ntiles; kt++) {
        const int j0 = kt * 128;
        __syncthreads();   // prior tile reads complete before overwrite

        // issue K (group 0) and V (group 1)
        {
            const __nv_bfloat16* k_h = Kh + (size_t)(j0 + lrow) * HD_ + lseg * 32;
            const __nv_bfloat16* k_l = Kl + (size_t)(j0 + lrow) * HD_ + lseg * 32;
            #pragma unroll
            for (int c = 0; c < 4; c++) {
                CP16(uS + 2*AK_H + rowb + c * 16, k_h + c * 8);
                CP16(uS + 2*AK_L + rowb + c * 16, k_l + c * 8);
            }
            CP_COMMIT();
            const __nv_bfloat16* v_h = Vh + (size_t)(j0 + lrow) * HD_ + lseg * 32;
            const __nv_bfloat16* v_l = Vl + (size_t)(j0 + lrow) * HD_ + lseg * 32;
            #pragma unroll
            for (int c = 0; c < 4; c++) {
                CP16(uS + 2*AV_H + rowb + c * 16, v_h + c * 8);
                CP16(uS + 2*AV_L + rowb + c * 16, v_l + c * 8);
            }
            CP_COMMIT();
        }
        CP_WAIT(1);        // K ready; V still in flight
        __syncthreads();

        // ---- QK: S[16 x 128] per warp ----
        float accS[16][4];
        #pragma unroll
        for (int i = 0; i < 16; i++)
            #pragma unroll
            for (int r = 0; r < 4; r++) accS[i][r] = 0.f;

        #pragma unroll
        for (int dk = 0; dk < 4; dk++) {
            #pragma unroll
            for (int jc = 0; jc < 8; jc++) {
                uint32_t kh[4], kl[4];
                const uint32_t off = 2u * ((jc * 16 + lrm) * APAD + dk * 16 + lck);
                LDSM4(kh, uS + 2*AK_H + off);
                LDSM4(kl, uS + 2*AK_L + off);
                MMA_BF16(accS[2*jc],   aQh[dk], kh[0], kh[2]);
                MMA_BF16(accS[2*jc+1], aQh[dk], kh[1], kh[3]);
                MMA_BF16(accS[2*jc],   aQh[dk], kl[0], kl[2]);
                MMA_BF16(accS[2*jc+1], aQh[dk], kl[1], kl[3]);
                MMA_BF16(accS[2*jc],   aQl[dk], kh[0], kh[2]);
                MMA_BF16(accS[2*jc+1], aQl[dk], kh[1], kh[3]);
            }
        }

        // ---- softmax (base-2, no MUFU) ----
        const bool diag = (kt == qt);
        float mx0 = -1e30f, mx1 = -1e30f;
        #pragma unroll
        for (int nt = 0; nt < 16; nt++) {
            const int jb = j0 + nt * 8 + (lane & 3) * 2;
            float c0 = accS[nt][0] * SC2_;
            float c1 = accS[nt][1] * SC2_;
            float c2 = accS[nt][2] * SC2_;
            float c3 = accS[nt][3] * SC2_;
            if (diag) {
                if (jb     > r0g) c0 = -1e30f;
                if (jb + 1 > r0g) c1 = -1e30f;
                if (jb     > r1g) c2 = -1e30f;
                if (jb + 1 > r1g) c3 = -1e30f;
            }
            accS[nt][0] = c0; accS[nt][1] = c1; accS[nt][2] = c2; accS[nt][3] = c3;
            mx0 = fmaxf(mx0, fmaxf(c0, c1));
            mx1 = fmaxf(mx1, fmaxf(c2, c3));
        }
        mx0 = fmaxf(mx0, __shfl_xor_sync(0xffffffffu, mx0, 1));
        mx0 = fmaxf(mx0, __shfl_xor_sync(0xffffffffu, mx0, 2));
        mx1 = fmaxf(mx1, __shfl_xor_sync(0xffffffffu, mx1, 1));
        mx1 = fmaxf(mx1, __shfl_xor_sync(0xffffffffu, mx1, 2));

        const float mn0 = fmaxf(m0s, mx0);
        const float mn1 = fmaxf(m1s, mx1);
        const float al0 = exp2f_fast(m0s - mn0);
        const float al1 = exp2f_fast(m1s - mn1);
        m0s = mn0; m1s = mn1;

        float ls0 = 0.f, ls1 = 0.f;
        #pragma unroll
        for (int nt = 0; nt < 16; nt++) {
            float p0 = exp2f_fast(accS[nt][0] - mn0);
            float p1 = exp2f_fast(accS[nt][1] - mn0);
            float p2 = exp2f_fast(accS[nt][2] - mn1);
            float p3 = exp2f_fast(accS[nt][3] - mn1);
            accS[nt][0] = p0; accS[nt][1] = p1; accS[nt][2] = p2; accS[nt][3] = p3;
            ls0 += p0 + p1;
            ls1 += p2 + p3;
        }
        ls0 += __shfl_xor_sync(0xffffffffu, ls0, 1);
        ls0 += __shfl_xor_sync(0xffffffffu, ls0, 2);
        ls1 += __shfl_xor_sync(0xffffffffu, ls1, 1);
        ls1 += __shfl_xor_sync(0xffffffffu, ls1, 2);
        l0s = l0s * al0 + ls0;
        l1s = l1s * al1 + ls1;

        #pragma unroll
        for (int i = 0; i < 8; i++) {
            accO[i][0] *= al0; accO[i][1] *= al0;
            accO[i][2] *= al1; accO[i][3] *= al1;
        }

        CP_WAIT(0);        // V ready
        __syncthreads();

        // ---- PV: accO += P @ V  (A-frags from accS; B via trans ldsm) ----
        #pragma unroll
        for (int kt2 = 0; kt2 < 8; kt2++) {
            uint32_t aPh[4], aPl[4];
            {
                const float p00 = accS[2*kt2][0],   p01 = accS[2*kt2][1];
                const float p02 = accS[2*kt2][2],   p03 = accS[2*kt2][3];
                const float p10 = accS[2*kt2+1][0], p11 = accS[2*kt2+1][1];
                const float p12 = accS[2*kt2+1][2], p13 = accS[2*kt2+1][3];
                aPh[0] = pack_bf16(p00, p01);
                aPh[1] = pack_bf16(p02, p03);
                aPh[2] = pack_bf16(p10, p11);
                aPh[3] = pack_bf16(p12, p13);
                aPl[0] = pack_bf16(p00 - __bfloat162float(__float2bfloat16(p00)),
                                   p01 - __bfloat162float(__float2bfloat16(p01)));
                aPl[1] = pack_bf16(p02 - __bfloat162float(__float2bfloat16(p02)),
                                   p03 - __bfloat162float(__float2bfloat16(p03)));
                aPl[2] = pack_bf16(p10 - __bfloat162float(__float2bfloat16(p10)),
                                   p11 - __bfloat162float(__float2bfloat16(p11)));
                aPl[3] = pack_bf16(p12 - __bfloat162float(__float2bfloat16(p12)),
                                   p13 - __bfloat162float(__float2bfloat16(p13)));
            }
            // lane address: V[j = kt2*16 + lane%16][e = (lane/16)*8 + g*16]
            const uint32_t vbase = 2u * ((kt2 * 16 + lrm) * APAD + lck);
            #pragma unroll
            for (int g = 0; g < 4; g++) {
                uint32_t vh[4], vl[4];
                const uint32_t off = vbase + 2u * (g * 16);
                LDSM4T(vh, uS + 2*AV_H + off);
                LDSM4T(vl, uS + 2*AV_L + off);
                MMA_BF16(accO[2*g],   aPh, vh[0], vh[1]);
                MMA_BF16(accO[2*g+1], aPh, vh[2], vh[3]);
                MMA_BF16(accO[2*g],   aPh, vl[0], vl[1]);
                MMA_BF16(accO[2*g+1], aPh, vl[2], vl[3]);
                MMA_BF16(accO[2*g],   aPl, vh[0], vh[1]);
                MMA_BF16(accO[2*g+1], aPl, vh[2], vh[3]);
            }
        }
    }

    // ---- epilogue: normalize, split hi/lo, write concat layout ----
    const int b = bh >> 4;
    const int h = bh & 15;
    const float inv0 = 1.f / l0s;
    const float inv1 = 1.f / l1s;
    #pragma unroll
    for (int nt = 0; nt < 8; nt++) {
        const int e = nt * 8 + (lane & 3) * 2;
        #pragma unroll
        for (int half = 0; half < 2; half++) {
            const int s = (half == 0) ? r0g : r1g;
            const float sc = (half == 0) ? inv0 : inv1;
            const float a0 = accO[nt][half * 2 + 0] * sc;
            const float a1 = accO[nt][half * 2 + 1] * sc;
            const size_t base = ((size_t)b * S_ + s) * D_ + h * HD_ + e;
            const float h0f = __bfloat162float(__float2bfloat16(a0));
            const float h1f = __bfloat162float(__float2bfloat16(a1));
            *(uint32_t*)&g_atth[base] = pack_bf16(a0, a1);
            *(uint32_t*)&g_attl[base] = pack_bf16(a0 - h0f, a1 - h1f);
        }
    }
}

// ---------------------------------------------------------------------------
// Launch
// ---------------------------------------------------------------------------
extern "C" void kernel_launch(void* const* d_in, const int* in_sizes, int n_in,
                              void* d_out, int out_size)
{
    const float* x  = (const float*)d_in[0];
    const float* Wq = (const float*)d_in[1];
    const float* Wk = (const float*)d_in[2];
    const float* Wv = (const float*)d_in[3];
    const float* Wp = (const float*)d_in[4];
    const float* bp = (const float*)d_in[5];
    float* out = (float*)d_out;
    (void)in_sizes; (void)n_in; (void)out_size;

    cudaFuncSetAttribute(gemm_mma,
                         cudaFuncAttributeMaxDynamicSharedMemorySize, GEMM_SMEM);
    cudaFuncSetAttribute(attn_mma_kernel,
                         cudaFuncAttributeMaxDynamicSharedMemorySize, ATT_SMEM);

    const int x4 = (B_ * S_ * D_) / 4;
    split_kernel<<<(x4 + 255) / 256, 256>>>(x, 0, x4);
    convw_kernel<<<(3 * H_ * HD_ * D_) / 256, 256>>>(Wq, Wk, Wv);
    const int w4 = (D_ * D_) / 4;
    split_kernel<<<(w4 + 255) / 256, 256>>>(Wp, 2, w4);

    // QKV: C[4096, 3072], 128x128 tiles -> bf16 hi/lo q/k/v
    gemm_mma<<<dim3((3 * H_ * HD_) / 128, (B_ * S_) / 128), 256, GEMM_SMEM>>>(
        0, nullptr, nullptr);

    // MMA flash attention -> g_atth/g_attl
    attn_mma_kernel<<<dim3(S_ / 128, B_ * H_), 256, ATT_SMEM>>>();

    // out projection
    gemm_mma<<<dim3(D_ / 128, (B_ * S_) / 128), 256, GEMM_SMEM>>>(1, bp, out);
}

// round 12
// speedup vs baseline: 3.3502x; 1.0633x over previous
#include <cuda_runtime.h>
#include <cuda_bf16.h>
#include <math.h>
#include <cstdint>

// Problem constants: B=2, S=2048, D=1024, H=16, HD=64
#define B_  2
#define S_  2048
#define D_  1024
#define H_  16
#define HD_ 64
#define SC2_   0.045084220f       // D^-0.5 * log2(e)
#define KTOT 1024

// ---------------------------------------------------------------------------
// Scratch (device globals)
// ---------------------------------------------------------------------------
__device__ __nv_bfloat16 g_qh[(size_t)B_*H_*S_*HD_], g_ql[(size_t)B_*H_*S_*HD_];
__device__ __nv_bfloat16 g_kh[(size_t)B_*H_*S_*HD_], g_kl[(size_t)B_*H_*S_*HD_];
__device__ __nv_bfloat16 g_vh[(size_t)B_*H_*S_*HD_], g_vl[(size_t)B_*H_*S_*HD_];
__device__ __nv_bfloat16 g_atth[(size_t)B_*S_*D_], g_attl[(size_t)B_*S_*D_];
__device__ __nv_bfloat16 g_xh[(size_t)B_*S_*D_],  g_xl[(size_t)B_*S_*D_];
__device__ __nv_bfloat16 g_wbh[(size_t)3*H_*HD_*D_], g_wbl[(size_t)3*H_*HD_*D_];
__device__ __nv_bfloat16 g_wph[(size_t)D_*D_],    g_wpl[(size_t)D_*D_];

// ---------------------------------------------------------------------------
// PTX helpers (sm_80+ only; compile clean under compute_103)
// ---------------------------------------------------------------------------
__device__ __forceinline__ uint32_t smem_to_u32(const void* p) {
    uint32_t a;
    asm("{ .reg .u64 t; cvta.to.shared.u64 t, %1; cvt.u32.u64 %0, t; }" : "=r"(a) : "l"(p));
    return a;
}
#define LDSM4(r, addr) \
    asm volatile("ldmatrix.sync.aligned.m8n8.x4.shared.b16 {%0,%1,%2,%3}, [%4];" \
        : "=r"((r)[0]), "=r"((r)[1]), "=r"((r)[2]), "=r"((r)[3]) : "r"(addr))
#define LDSM4T(r, addr) \
    asm volatile("ldmatrix.sync.aligned.m8n8.x4.trans.shared.b16 {%0,%1,%2,%3}, [%4];" \
        : "=r"((r)[0]), "=r"((r)[1]), "=r"((r)[2]), "=r"((r)[3]) : "r"(addr))
#define MMA_BF16(c, a, b0, b1) \
    asm volatile("mma.sync.aligned.m16n8k16.row.col.f32.bf16.bf16.f32 " \
        "{%0,%1,%2,%3}, {%4,%5,%6,%7}, {%8,%9}, {%0,%1,%2,%3};" \
        : "+f"((c)[0]), "+f"((c)[1]), "+f"((c)[2]), "+f"((c)[3]) \
        : "r"((a)[0]), "r"((a)[1]), "r"((a)[2]), "r"((a)[3]), "r"(b0), "r"(b1))
#define CP16(saddr, gptr) \
    asm volatile("cp.async.cg.shared.global [%0], [%1], 16;" \
        :: "r"((uint32_t)(saddr)), "l"(gptr))
#define CP_COMMIT() asm volatile("cp.async.commit_group;" ::: "memory")
#define CP_WAIT(n)  asm volatile("cp.async.wait_group %0;" :: "n"(n) : "memory")

__device__ __forceinline__ uint32_t pack_bf16(float lo, float hi) {
    __nv_bfloat162 t = __floats2bfloat162_rn(lo, hi);
    return *(uint32_t*)&t;
}
// fast exp2: rint split + deg-5 poly; input always <= 0.
__device__ __forceinline__ float exp2f_fast(float t) {
    t = fmaxf(t, -120.f);
    int ni = __float2int_rn(t);
    float f = t - (float)ni;
    float r = 1.f + f * (0.69314718f + f * (0.24022651f + f * (0.05550411f
               + f * (0.00961812f + f * 0.00133336f))));
    return r * __int_as_float((ni + 127) << 23);
}

// ---------------------------------------------------------------------------
// Split kernels: fp32 -> bf16 hi + bf16 residual
// ---------------------------------------------------------------------------
__global__ __launch_bounds__(256) void split_kernel(const float* __restrict__ src,
                                                    int mode, int n4)
{
    int i = blockIdx.x * 256 + threadIdx.x;
    if (i >= n4) return;
    __nv_bfloat16* dh = (mode == 0) ? g_xh : g_wph;
    __nv_bfloat16* dl = (mode == 0) ? g_xl : g_wpl;

    float4 v = ((const float4*)src)[i];
    __nv_bfloat16 h0 = __float2bfloat16(v.x);
    __nv_bfloat16 h1 = __float2bfloat16(v.y);
    __nv_bfloat16 h2 = __float2bfloat16(v.z);
    __nv_bfloat16 h3 = __float2bfloat16(v.w);
    __nv_bfloat16 l0 = __float2bfloat16(v.x - __bfloat162float(h0));
    __nv_bfloat16 l1 = __float2bfloat16(v.y - __bfloat162float(h1));
    __nv_bfloat16 l2 = __float2bfloat16(v.z - __bfloat162float(h2));
    __nv_bfloat16 l3 = __float2bfloat16(v.w - __bfloat162float(h3));
    __nv_bfloat16 hs[4] = {h0, h1, h2, h3};
    __nv_bfloat16 ls[4] = {l0, l1, l2, l3};
    ((uint2*)dh)[i] = *(uint2*)hs;
    ((uint2*)dl)[i] = *(uint2*)ls;
}

__global__ __launch_bounds__(256) void convw_kernel(const float* __restrict__ Wq,
                                                    const float* __restrict__ Wk,
                                                    const float* __restrict__ Wv)
{
    size_t idx = (size_t)blockIdx.x * 256 + threadIdx.x;
    int n = (int)(idx >> 10);
    int k = (int)(idx & 1023);
    int which = n >> 10;
    int h = (n >> 6) & 15;
    int e = n & 63;
    const float* W = (which == 0 ? Wq : which == 1 ? Wk : Wv);
    float v = W[((size_t)h * D_ + k) * HD_ + e];
    __nv_bfloat16 hi = __float2bfloat16(v);
    __nv_bfloat16 lo = __float2bfloat16(v - __bfloat162float(hi));
    g_wbh[idx] = hi;
    g_wbl[idx] = lo;
}

// ---------------------------------------------------------------------------
// Warp-MMA GEMM, bf16x3 split, cp.async 3-stage pipeline, ONE sync per chunk.
// SMEM: unpadded 128x32 tiles with 16B-chunk XOR swizzle (ldsm conflict-free).
// mode 0: QKV (emit bf16 hi/lo q/k/v)   mode 1: out-proj (+bias, fp32 out)
// ---------------------------------------------------------------------------
#define NST 3
#define TB_AH 0
#define TB_AL 8192
#define TB_BH 16384
#define TB_BL 24576
#define STG_B 32768
#define GEMM_SMEM (NST * STG_B)   // 98304

// byte offset of 16B chunk inside a 128-row x 32-elem tile (row stride 64B)
__device__ __forceinline__ uint32_t swz(int row, int chunk) {
    int sw = chunk ^ ((row >> 1) & 3) ^ ((row >> 3) & 1);
    return (uint32_t)((row << 6) + (sw << 4));
}

__global__ __launch_bounds__(256, 2) void gemm_mma(int mode,
                                                   const float* __restrict__ bias,
                                                   float* __restrict__ Cout)
{
    extern __shared__ __nv_bfloat16 dsm[];
    const uint32_t ub = smem_to_u32(dsm);

    const int tid  = threadIdx.x;
    const int lane = tid & 31;
    const int wid  = tid >> 5;
    const int warp_m = wid >> 2;
    const int warp_n = wid & 3;
    const int n0 = blockIdx.x * 128;
    const int m0 = blockIdx.y * 128;

    const __nv_bfloat16* Ah = mode ? g_atth : g_xh;
    const __nv_bfloat16* Al = mode ? g_attl : g_xl;
    const __nv_bfloat16* Bh = mode ? g_wph  : g_wbh;
    const __nv_bfloat16* Bl = mode ? g_wpl  : g_wbl;

    const int lrow = tid >> 1;          // 0..127
    const int lseg = tid & 1;           // handles chunks {2*lseg, 2*lseg+1}
    const __nv_bfloat16* ga_h = Ah + (size_t)(m0 + lrow) * KTOT;
    const __nv_bfloat16* ga_l = Al + (size_t)(m0 + lrow) * KTOT;
    const __nv_bfloat16* gb_h = Bh + (size_t)(n0 + lrow) * KTOT;
    const __nv_bfloat16* gb_l = Bl + (size_t)(n0 + lrow) * KTOT;
    const uint32_t s0 = swz(lrow, 2 * lseg);       // chunk 2*lseg
    const uint32_t s1 = swz(lrow, 2 * lseg + 1);   // chunk 2*lseg+1
    const int gofs = lseg * 16;                    // elem offset of chunk pair

    const int lrm = lane & 15;
    const int lck = (lane >> 4);        // 0/1 -> chunk parity for ldsm

    float acc[4][4][4];
    #pragma unroll
    for (int i = 0; i < 4; i++)
        #pragma unroll
        for (int j = 0; j < 4; j++)
            #pragma unroll
            for (int r = 0; r < 4; r++) acc[i][j][r] = 0.f;

    // ---- prologue: stages 0 and 1 ----
    #pragma unroll
    for (int ps = 0; ps < 2; ps++) {
        const uint32_t sb = ub + ps * STG_B;
        const int k0 = ps * 32 + gofs;
        CP16(sb + TB_AH + s0, ga_h + k0);      CP16(sb + TB_AH + s1, ga_h + k0 + 8);
        CP16(sb + TB_AL + s0, ga_l + k0);      CP16(sb + TB_AL + s1, ga_l + k0 + 8);
        CP16(sb + TB_BH + s0, gb_h + k0);      CP16(sb + TB_BH + s1, gb_h + k0 + 8);
        CP16(sb + TB_BL + s0, gb_l + k0);      CP16(sb + TB_BL + s1, gb_l + k0 + 8);
        CP_COMMIT();
    }

    const int NKC = KTOT / 32;
    int slot = 0, wslot = 2;
    for (int kc = 0; kc < NKC; kc++) {
        CP_WAIT(1);            // stage kc complete
        __syncthreads();       // all warps done reading slot being refilled

        // issue stage kc+2 into slot (kc+2)%3 (read last at iter kc-1 -> safe)
        if (kc + 2 < NKC) {
            const uint32_t sb = ub + wslot * STG_B;
            const int k0 = (kc + 2) * 32 + gofs;
            CP16(sb + TB_AH + s0, ga_h + k0);      CP16(sb + TB_AH + s1, ga_h + k0 + 8);
            CP16(sb + TB_AL + s0, ga_l + k0);      CP16(sb + TB_AL + s1, ga_l + k0 + 8);
            CP16(sb + TB_BH + s0, gb_h + k0);      CP16(sb + TB_BH + s1, gb_h + k0 + 8);
            CP16(sb + TB_BL + s0, gb_l + k0);      CP16(sb + TB_BL + s1, gb_l + k0 + 8);
        }
        CP_COMMIT();

        const uint32_t us = ub + slot * STG_B;
        #pragma unroll
        for (int ks = 0; ks < 2; ks++) {
            const int chunk = ks * 2 + lck;     // this lane-half's 16B chunk
            uint32_t afh[4][4], afl[4][4];
            uint32_t bfh[2][4], bfl[2][4];
            #pragma unroll
            for (int mt = 0; mt < 4; mt++) {
                const uint32_t off = swz(warp_m * 64 + mt * 16 + lrm, chunk);
                LDSM4(afh[mt], us + TB_AH + off);
                LDSM4(afl[mt], us + TB_AL + off);
            }
            #pragma unroll
            for (int np = 0; np < 2; np++) {
                const uint32_t off = swz(warp_n * 32 + np * 16 + lrm, chunk);
                LDSM4(bfh[np], us + TB_BH + off);
                LDSM4(bfl[np], us + TB_BL + off);
            }
            #pragma unroll
            for (int mt = 0; mt < 4; mt++) {
                #pragma unroll
                for (int nt = 0; nt < 4; nt++) {
                    const int np = nt >> 1, sel = nt & 1;
                    MMA_BF16(acc[mt][nt], afh[mt], bfh[np][sel], bfh[np][sel + 2]);
                    MMA_BF16(acc[mt][nt], afh[mt], bfl[np][sel], bfl[np][sel + 2]);
                    MMA_BF16(acc[mt][nt], afl[mt], bfh[np][sel], bfh[np][sel + 2]);
                }
            }
        }
        slot = (slot == 2) ? 0 : slot + 1;
        wslot = (wslot == 2) ? 0 : wslot + 1;
    }

    // ------------------------------ epilogue ------------------------------
    #pragma unroll
    for (int mt = 0; mt < 4; mt++) {
        #pragma unroll
        for (int nt = 0; nt < 4; nt++) {
            const int mrow = m0 + warp_m * 64 + mt * 16 + (lane >> 2);
            const int ncol = n0 + warp_n * 32 + nt * 8 + (lane & 3) * 2;
            if (mode == 1) {
                const float b0 = bias[ncol], b1 = bias[ncol + 1];
                float2 v0 = make_float2(acc[mt][nt][0] + b0, acc[mt][nt][1] + b1);
                float2 v1 = make_float2(acc[mt][nt][2] + b0, acc[mt][nt][3] + b1);
                *(float2*)(Cout + (size_t)mrow * D_ + ncol)       = v0;
                *(float2*)(Cout + (size_t)(mrow + 8) * D_ + ncol) = v1;
            } else {
                const int which = ncol >> 10;
                const int h = (ncol >> 6) & 15;
                const int e = ncol & 63;
                __nv_bfloat16* bhp = (which == 0 ? g_qh : which == 1 ? g_kh : g_vh);
                __nv_bfloat16* blp = (which == 0 ? g_ql : which == 1 ? g_kl : g_vl);
                #pragma unroll
                for (int half = 0; half < 2; half++) {
                    const int mr = mrow + half * 8;
                    const float a0 = acc[mt][nt][half * 2 + 0];
                    const float a1 = acc[mt][nt][half * 2 + 1];
                    const int b = mr >> 11, s = mr & 2047;
                    const size_t base = (((size_t)(b * H_ + h) * S_) + s) * HD_ + e;
                    const float h0f = __bfloat162float(__float2bfloat16(a0));
                    const float h1f = __bfloat162float(__float2bfloat16(a1));
                    *(uint32_t*)&bhp[base] = pack_bf16(a0, a1);
                    *(uint32_t*)&blp[base] = pack_bf16(a0 - h0f, a1 - h1f);
                }
            }
        }
    }
}

// ---------------------------------------------------------------------------
// MMA flash attention (unchanged from R10 passing version).
// ---------------------------------------------------------------------------
#define APAD 72
#define AK_H 0
#define AK_L (128 * APAD)
#define AV_H (2 * 128 * APAD)
#define AV_L (3 * 128 * APAD)
#define ATT_SMEM (4 * 128 * APAD * 2)          // 73728 bytes

__global__ __launch_bounds__(256) void attn_mma_kernel()
{
    extern __shared__ __nv_bfloat16 sm[];
    const uint32_t uS = smem_to_u32(sm);
    const int qt  = (int)gridDim.x - 1 - (int)blockIdx.x;   // heavy blocks first
    const int bh  = blockIdx.y;
    const int tid = threadIdx.x;
    const int lane = tid & 31;
    const int wid  = tid >> 5;
    const int m0g = qt * 128;

    const __nv_bfloat16* Qh = g_qh + (size_t)bh * S_ * HD_;
    const __nv_bfloat16* Ql = g_ql + (size_t)bh * S_ * HD_;
    const __nv_bfloat16* Kh = g_kh + (size_t)bh * S_ * HD_;
    const __nv_bfloat16* Kl = g_kl + (size_t)bh * S_ * HD_;
    const __nv_bfloat16* Vh = g_vh + (size_t)bh * S_ * HD_;
    const __nv_bfloat16* Vl = g_vl + (size_t)bh * S_ * HD_;

    const int lrow = tid >> 1;          // 0..127
    const int lseg = tid & 1;
    const int lrm  = lane & 15;
    const int lck  = (lane >> 4) * 8;
    const uint32_t rowb = 2u * (lrow * APAD + lseg * 32);   // byte offset of half-row

    // ---- stage Q into K-buffer via cp.async, build Q fragments ----
    {
        const __nv_bfloat16* q_h = Qh + (size_t)(m0g + lrow) * HD_ + lseg * 32;
        const __nv_bfloat16* q_l = Ql + (size_t)(m0g + lrow) * HD_ + lseg * 32;
        #pragma unroll
        for (int c = 0; c < 4; c++) {
            CP16(uS + 2*AK_H + rowb + c * 16, q_h + c * 8);
            CP16(uS + 2*AK_L + rowb + c * 16, q_l + c * 8);
        }
        CP_COMMIT();
        CP_WAIT(0);
        __syncthreads();
    }
    uint32_t aQh[4][4], aQl[4][4];
    #pragma unroll
    for (int dk = 0; dk < 4; dk++) {
        const uint32_t off = 2u * ((wid * 16 + lrm) * APAD + dk * 16 + lck);
        LDSM4(aQh[dk], uS + 2*AK_H + off);
        LDSM4(aQl[dk], uS + 2*AK_L + off);
    }

    float accO[8][4];
    #pragma unroll
    for (int i = 0; i < 8; i++)
        #pragma unroll
        for (int r = 0; r < 4; r++) accO[i][r] = 0.f;
    float m0s = -1e30f, m1s = -1e30f, l0s = 0.f, l1s = 0.f;

    const int r0g = m0g + wid * 16 + (lane >> 2);
    const int r1g = r0g + 8;
    const int ntiles = qt + 1;

    for (int kt = 0; kt < ntiles; kt++) {
        const int j0 = kt * 128;
        __syncthreads();   // prior tile reads complete before overwrite

        // issue K (group 0) and V (group 1)
        {
            const __nv_bfloat16* k_h = Kh + (size_t)(j0 + lrow) * HD_ + lseg * 32;
            const __nv_bfloat16* k_l = Kl + (size_t)(j0 + lrow) * HD_ + lseg * 32;
            #pragma unroll
            for (int c = 0; c < 4; c++) {
                CP16(uS + 2*AK_H + rowb + c * 16, k_h + c * 8);
                CP16(uS + 2*AK_L + rowb + c * 16, k_l + c * 8);
            }
            CP_COMMIT();
            const __nv_bfloat16* v_h = Vh + (size_t)(j0 + lrow) * HD_ + lseg * 32;
            const __nv_bfloat16* v_l = Vl + (size_t)(j0 + lrow) * HD_ + lseg * 32;
            #pragma unroll
            for (int c = 0; c < 4; c++) {
                CP16(uS + 2*AV_H + rowb + c * 16, v_h + c * 8);
                CP16(uS + 2*AV_L + rowb + c * 16, v_l + c * 8);
            }
            CP_COMMIT();
        }
        CP_WAIT(1);        // K ready; V still in flight
        __syncthreads();

        // ---- QK: S[16 x 128] per warp ----
        float accS[16][4];
        #pragma unroll
        for (int i = 0; i < 16; i++)
            #pragma unroll
            for (int r = 0; r < 4; r++) accS[i][r] = 0.f;

        #pragma unroll
        for (int dk = 0; dk < 4; dk++) {
            #pragma unroll
            for (int jc = 0; jc < 8; jc++) {
                uint32_t kh[4], kl[4];
                const uint32_t off = 2u * ((jc * 16 + lrm) * APAD + dk * 16 + lck);
                LDSM4(kh, uS + 2*AK_H + off);
                LDSM4(kl, uS + 2*AK_L + off);
                MMA_BF16(accS[2*jc],   aQh[dk], kh[0], kh[2]);
                MMA_BF16(accS[2*jc+1], aQh[dk], kh[1], kh[3]);
                MMA_BF16(accS[2*jc],   aQh[dk], kl[0], kl[2]);
                MMA_BF16(accS[2*jc+1], aQh[dk], kl[1], kl[3]);
                MMA_BF16(accS[2*jc],   aQl[dk], kh[0], kh[2]);
                MMA_BF16(accS[2*jc+1], aQl[dk], kh[1], kh[3]);
            }
        }

        // ---- softmax (base-2, no MUFU) ----
        const bool diag = (kt == qt);
        float mx0 = -1e30f, mx1 = -1e30f;
        #pragma unroll
        for (int nt = 0; nt < 16; nt++) {
            const int jb = j0 + nt * 8 + (lane & 3) * 2;
            float c0 = accS[nt][0] * SC2_;
            float c1 = accS[nt][1] * SC2_;
            float c2 = accS[nt][2] * SC2_;
            float c3 = accS[nt][3] * SC2_;
            if (diag) {
                if (jb     > r0g) c0 = -1e30f;
                if (jb + 1 > r0g) c1 = -1e30f;
                if (jb     > r1g) c2 = -1e30f;
                if (jb + 1 > r1g) c3 = -1e30f;
            }
            accS[nt][0] = c0; accS[nt][1] = c1; accS[nt][2] = c2; accS[nt][3] = c3;
            mx0 = fmaxf(mx0, fmaxf(c0, c1));
            mx1 = fmaxf(mx1, fmaxf(c2, c3));
        }
        mx0 = fmaxf(mx0, __shfl_xor_sync(0xffffffffu, mx0, 1));
        mx0 = fmaxf(mx0, __shfl_xor_sync(0xffffffffu, mx0, 2));
        mx1 = fmaxf(mx1, __shfl_xor_sync(0xffffffffu, mx1, 1));
        mx1 = fmaxf(mx1, __shfl_xor_sync(0xffffffffu, mx1, 2));

        const float mn0 = fmaxf(m0s, mx0);
        const float mn1 = fmaxf(m1s, mx1);
        const float al0 = exp2f_fast(m0s - mn0);
        const float al1 = exp2f_fast(m1s - mn1);
        m0s = mn0; m1s = mn1;

        float ls0 = 0.f, ls1 = 0.f;
        #pragma unroll
        for (int nt = 0; nt < 16; nt++) {
            float p0 = exp2f_fast(accS[nt][0] - mn0);
            float p1 = exp2f_fast(accS[nt][1] - mn0);
            float p2 = exp2f_fast(accS[nt][2] - mn1);
            float p3 = exp2f_fast(accS[nt][3] - mn1);
            accS[nt][0] = p0; accS[nt][1] = p1; accS[nt][2] = p2; accS[nt][3] = p3;
            ls0 += p0 + p1;
            ls1 += p2 + p3;
        }
        ls0 += __shfl_xor_sync(0xffffffffu, ls0, 1);
        ls0 += __shfl_xor_sync(0xffffffffu, ls0, 2);
        ls1 += __shfl_xor_sync(0xffffffffu, ls1, 1);
        ls1 += __shfl_xor_sync(0xffffffffu, ls1, 2);
        l0s = l0s * al0 + ls0;
        l1s = l1s * al1 + ls1;

        #pragma unroll
        for (int i = 0; i < 8; i++) {
            accO[i][0] *= al0; accO[i][1] *= al0;
            accO[i][2] *= al1; accO[i][3] *= al1;
        }

        CP_WAIT(0);        // V ready
        __syncthreads();

        // ---- PV: accO += P @ V  (A-frags from accS; B via trans ldsm) ----
        #pragma unroll
        for (int kt2 = 0; kt2 < 8; kt2++) {
            uint32_t aPh[4], aPl[4];
            {
                const float p00 = accS[2*kt2][0],   p01 = accS[2*kt2][1];
                const float p02 = accS[2*kt2][2],   p03 = accS[2*kt2][3];
                const float p10 = accS[2*kt2+1][0], p11 = accS[2*kt2+1][1];
                const float p12 = accS[2*kt2+1][2], p13 = accS[2*kt2+1][3];
                aPh[0] = pack_bf16(p00, p01);
                aPh[1] = pack_bf16(p02, p03);
                aPh[2] = pack_bf16(p10, p11);
                aPh[3] = pack_bf16(p12, p13);
                aPl[0] = pack_bf16(p00 - __bfloat162float(__float2bfloat16(p00)),
                                   p01 - __bfloat162float(__float2bfloat16(p01)));
                aPl[1] = pack_bf16(p02 - __bfloat162float(__float2bfloat16(p02)),
                                   p03 - __bfloat162float(__float2bfloat16(p03)));
                aPl[2] = pack_bf16(p10 - __bfloat162float(__float2bfloat16(p10)),
                                   p11 - __bfloat162float(__float2bfloat16(p11)));
                aPl[3] = pack_bf16(p12 - __bfloat162float(__float2bfloat16(p12)),
                                   p13 - __bfloat162float(__float2bfloat16(p13)));
            }
            // lane address: V[j = kt2*16 + lane%16][e = (lane/16)*8 + g*16]
            const uint32_t vbase = 2u * ((kt2 * 16 + lrm) * APAD + lck);
            #pragma unroll
            for (int g = 0; g < 4; g++) {
                uint32_t vh[4], vl[4];
                const uint32_t off = vbase + 2u * (g * 16);
                LDSM4T(vh, uS + 2*AV_H + off);
                LDSM4T(vl, uS + 2*AV_L + off);
                MMA_BF16(accO[2*g],   aPh, vh[0], vh[1]);
                MMA_BF16(accO[2*g+1], aPh, vh[2], vh[3]);
                MMA_BF16(accO[2*g],   aPh, vl[0], vl[1]);
                MMA_BF16(accO[2*g+1], aPh, vl[2], vl[3]);
                MMA_BF16(accO[2*g],   aPl, vh[0], vh[1]);
                MMA_BF16(accO[2*g+1], aPl, vh[2], vh[3]);
            }
        }
    }

    // ---- epilogue: normalize, split hi/lo, write concat layout ----
    const int b = bh >> 4;
    const int h = bh & 15;
    const float inv0 = 1.f / l0s;
    const float inv1 = 1.f / l1s;
    #pragma unroll
    for (int nt = 0; nt < 8; nt++) {
        const int e = nt * 8 + (lane & 3) * 2;
        #pragma unroll
        for (int half = 0; half < 2; half++) {
            const int s = (half == 0) ? r0g : r1g;
            const float sc = (half == 0) ? inv0 : inv1;
            const float a0 = accO[nt][half * 2 + 0] * sc;
            const float a1 = accO[nt][half * 2 + 1] * sc;
            const size_t base = ((size_t)b * S_ + s) * D_ + h * HD_ + e;
            const float h0f = __bfloat162float(__float2bfloat16(a0));
            const float h1f = __bfloat162float(__float2bfloat16(a1));
            *(uint32_t*)&g_atth[base] = pack_bf16(a0, a1);
            *(uint32_t*)&g_attl[base] = pack_bf16(a0 - h0f, a1 - h1f);
        }
    }
}

// ---------------------------------------------------------------------------
// Launch
// ---------------------------------------------------------------------------
extern "C" void kernel_launch(void* const* d_in, const int* in_sizes, int n_in,
                              void* d_out, int out_size)
{
    const float* x  = (const float*)d_in[0];
    const float* Wq = (const float*)d_in[1];
    const float* Wk = (const float*)d_in[2];
    const float* Wv = (const float*)d_in[3];
    const float* Wp = (const float*)d_in[4];
    const float* bp = (const float*)d_in[5];
    float* out = (float*)d_out;
    (void)in_sizes; (void)n_in; (void)out_size;

    cudaFuncSetAttribute(gemm_mma,
                         cudaFuncAttributeMaxDynamicSharedMemorySize, GEMM_SMEM);
    cudaFuncSetAttribute(attn_mma_kernel,
                         cudaFuncAttributeMaxDynamicSharedMemorySize, ATT_SMEM);

    const int x4 = (B_ * S_ * D_) / 4;
    split_kernel<<<(x4 + 255) / 256, 256>>>(x, 0, x4);
    convw_kernel<<<(3 * H_ * HD_ * D_) / 256, 256>>>(Wq, Wk, Wv);
    const int w4 = (D_ * D_) / 4;
    split_kernel<<<(w4 + 255) / 256, 256>>>(Wp, 2, w4);

    // QKV: C[4096, 3072], 128x128 tiles -> bf16 hi/lo q/k/v
    gemm_mma<<<dim3((3 * H_ * HD_) / 128, (B_ * S_) / 128), 256, GEMM_SMEM>>>(
        0, nullptr, nullptr);

    // MMA flash attention -> g_atth/g_attl
    attn_mma_kernel<<<dim3(S_ / 128, B_ * H_), 256, ATT_SMEM>>>();

    // out projection
    gemm_mma<<<dim3(D_ / 128, (B_ * S_) / 128), 256, GEMM_SMEM>>>(1, bp, out);
}

// round 13
// speedup vs baseline: 3.4606x; 1.0329x over previous
#include <cuda_runtime.h>
#include <cuda_bf16.h>
#include <math.h>
#include <cstdint>

// Problem constants: B=2, S=2048, D=1024, H=16, HD=64
#define B_  2
#define S_  2048
#define D_  1024
#define H_  16
#define HD_ 64
#define SC2_   0.045084220f       // D^-0.5 * log2(e)
#define KTOT 1024

// ---------------------------------------------------------------------------
// Scratch (device globals)
// ---------------------------------------------------------------------------
__device__ __nv_bfloat16 g_qh[(size_t)B_*H_*S_*HD_], g_ql[(size_t)B_*H_*S_*HD_];
__device__ __nv_bfloat16 g_kh[(size_t)B_*H_*S_*HD_], g_kl[(size_t)B_*H_*S_*HD_];
__device__ __nv_bfloat16 g_vh[(size_t)B_*H_*S_*HD_], g_vl[(size_t)B_*H_*S_*HD_];
__device__ __nv_bfloat16 g_atth[(size_t)B_*S_*D_], g_attl[(size_t)B_*S_*D_];
__device__ __nv_bfloat16 g_xh[(size_t)B_*S_*D_],  g_xl[(size_t)B_*S_*D_];
__device__ __nv_bfloat16 g_wbh[(size_t)3*H_*HD_*D_], g_wbl[(size_t)3*H_*HD_*D_];
__device__ __nv_bfloat16 g_wph[(size_t)D_*D_],    g_wpl[(size_t)D_*D_];

// ---------------------------------------------------------------------------
// PTX helpers (sm_80+ only; compile clean under compute_103)
// ---------------------------------------------------------------------------
__device__ __forceinline__ uint32_t smem_to_u32(const void* p) {
    uint32_t a;
    asm("{ .reg .u64 t; cvta.to.shared.u64 t, %1; cvt.u32.u64 %0, t; }" : "=r"(a) : "l"(p));
    return a;
}
#define LDSM4(r, addr) \
    asm volatile("ldmatrix.sync.aligned.m8n8.x4.shared.b16 {%0,%1,%2,%3}, [%4];" \
        : "=r"((r)[0]), "=r"((r)[1]), "=r"((r)[2]), "=r"((r)[3]) : "r"(addr))
#define LDSM4T(r, addr) \
    asm volatile("ldmatrix.sync.aligned.m8n8.x4.trans.shared.b16 {%0,%1,%2,%3}, [%4];" \
        : "=r"((r)[0]), "=r"((r)[1]), "=r"((r)[2]), "=r"((r)[3]) : "r"(addr))
#define MMA_BF16(c, a, b0, b1) \
    asm volatile("mma.sync.aligned.m16n8k16.row.col.f32.bf16.bf16.f32 " \
        "{%0,%1,%2,%3}, {%4,%5,%6,%7}, {%8,%9}, {%0,%1,%2,%3};" \
        : "+f"((c)[0]), "+f"((c)[1]), "+f"((c)[2]), "+f"((c)[3]) \
        : "r"((a)[0]), "r"((a)[1]), "r"((a)[2]), "r"((a)[3]), "r"(b0), "r"(b1))
#define CP16(saddr, gptr) \
    asm volatile("cp.async.cg.shared.global [%0], [%1], 16;" \
        :: "r"((uint32_t)(saddr)), "l"(gptr))
#define CP_COMMIT() asm volatile("cp.async.commit_group;" ::: "memory")
#define CP_WAIT(n)  asm volatile("cp.async.wait_group %0;" :: "n"(n) : "memory")

__device__ __forceinline__ uint32_t pack_bf16(float lo, float hi) {
    __nv_bfloat162 t = __floats2bfloat162_rn(lo, hi);
    return *(uint32_t*)&t;
}
// fast exp2: rint split + deg-5 poly; input always <= 0.
__device__ __forceinline__ float exp2f_fast(float t) {
    t = fmaxf(t, -120.f);
    int ni = __float2int_rn(t);
    float f = t - (float)ni;
    float r = 1.f + f * (0.69314718f + f * (0.24022651f + f * (0.05550411f
               + f * (0.00961812f + f * 0.00133336f))));
    return r * __int_as_float((ni + 127) << 23);
}

// ---------------------------------------------------------------------------
// Split kernels: fp32 -> bf16 hi + bf16 residual
// ---------------------------------------------------------------------------
__global__ __launch_bounds__(256) void split_kernel(const float* __restrict__ src,
                                                    int mode, int n4)
{
    int i = blockIdx.x * 256 + threadIdx.x;
    if (i >= n4) return;
    __nv_bfloat16* dh = (mode == 0) ? g_xh : g_wph;
    __nv_bfloat16* dl = (mode == 0) ? g_xl : g_wpl;

    float4 v = ((const float4*)src)[i];
    __nv_bfloat16 h0 = __float2bfloat16(v.x);
    __nv_bfloat16 h1 = __float2bfloat16(v.y);
    __nv_bfloat16 h2 = __float2bfloat16(v.z);
    __nv_bfloat16 h3 = __float2bfloat16(v.w);
    __nv_bfloat16 l0 = __float2bfloat16(v.x - __bfloat162float(h0));
    __nv_bfloat16 l1 = __float2bfloat16(v.y - __bfloat162float(h1));
    __nv_bfloat16 l2 = __float2bfloat16(v.z - __bfloat162float(h2));
    __nv_bfloat16 l3 = __float2bfloat16(v.w - __bfloat162float(h3));
    __nv_bfloat16 hs[4] = {h0, h1, h2, h3};
    __nv_bfloat16 ls[4] = {l0, l1, l2, l3};
    ((uint2*)dh)[i] = *(uint2*)hs;
    ((uint2*)dl)[i] = *(uint2*)ls;
}

__global__ __launch_bounds__(256) void convw_kernel(const float* __restrict__ Wq,
                                                    const float* __restrict__ Wk,
                                                    const float* __restrict__ Wv)
{
    size_t idx = (size_t)blockIdx.x * 256 + threadIdx.x;
    int n = (int)(idx >> 10);
    int k = (int)(idx & 1023);
    int which = n >> 10;
    int h = (n >> 6) & 15;
    int e = n & 63;
    const float* W = (which == 0 ? Wq : which == 1 ? Wk : Wv);
    float v = W[((size_t)h * D_ + k) * HD_ + e];
    __nv_bfloat16 hi = __float2bfloat16(v);
    __nv_bfloat16 lo = __float2bfloat16(v - __bfloat162float(hi));
    g_wbh[idx] = hi;
    g_wbl[idx] = lo;
}

// ---------------------------------------------------------------------------
// Warp-MMA GEMM, bf16x3 split, cp.async 3-stage pipeline (unchanged from R12).
// ---------------------------------------------------------------------------
#define NST 3
#define TB_AH 0
#define TB_AL 8192
#define TB_BH 16384
#define TB_BL 24576
#define STG_B 32768
#define GEMM_SMEM (NST * STG_B)   // 98304

__device__ __forceinline__ uint32_t swz(int row, int chunk) {
    int sw = chunk ^ ((row >> 1) & 3) ^ ((row >> 3) & 1);
    return (uint32_t)((row << 6) + (sw << 4));
}

__global__ __launch_bounds__(256, 2) void gemm_mma(int mode,
                                                   const float* __restrict__ bias,
                                                   float* __restrict__ Cout)
{
    extern __shared__ __nv_bfloat16 dsm[];
    const uint32_t ub = smem_to_u32(dsm);

    const int tid  = threadIdx.x;
    const int lane = tid & 31;
    const int wid  = tid >> 5;
    const int warp_m = wid >> 2;
    const int warp_n = wid & 3;
    const int n0 = blockIdx.x * 128;
    const int m0 = blockIdx.y * 128;

    const __nv_bfloat16* Ah = mode ? g_atth : g_xh;
    const __nv_bfloat16* Al = mode ? g_attl : g_xl;
    const __nv_bfloat16* Bh = mode ? g_wph  : g_wbh;
    const __nv_bfloat16* Bl = mode ? g_wpl  : g_wbl;

    const int lrow = tid >> 1;
    const int lseg = tid & 1;
    const __nv_bfloat16* ga_h = Ah + (size_t)(m0 + lrow) * KTOT;
    const __nv_bfloat16* ga_l = Al + (size_t)(m0 + lrow) * KTOT;
    const __nv_bfloat16* gb_h = Bh + (size_t)(n0 + lrow) * KTOT;
    const __nv_bfloat16* gb_l = Bl + (size_t)(n0 + lrow) * KTOT;
    const uint32_t s0 = swz(lrow, 2 * lseg);
    const uint32_t s1 = swz(lrow, 2 * lseg + 1);
    const int gofs = lseg * 16;

    const int lrm = lane & 15;
    const int lck = (lane >> 4);

    float acc[4][4][4];
    #pragma unroll
    for (int i = 0; i < 4; i++)
        #pragma unroll
        for (int j = 0; j < 4; j++)
            #pragma unroll
            for (int r = 0; r < 4; r++) acc[i][j][r] = 0.f;

    #pragma unroll
    for (int ps = 0; ps < 2; ps++) {
        const uint32_t sb = ub + ps * STG_B;
        const int k0 = ps * 32 + gofs;
        CP16(sb + TB_AH + s0, ga_h + k0);      CP16(sb + TB_AH + s1, ga_h + k0 + 8);
        CP16(sb + TB_AL + s0, ga_l + k0);      CP16(sb + TB_AL + s1, ga_l + k0 + 8);
        CP16(sb + TB_BH + s0, gb_h + k0);      CP16(sb + TB_BH + s1, gb_h + k0 + 8);
        CP16(sb + TB_BL + s0, gb_l + k0);      CP16(sb + TB_BL + s1, gb_l + k0 + 8);
        CP_COMMIT();
    }

    const int NKC = KTOT / 32;
    int slot = 0, wslot = 2;
    for (int kc = 0; kc < NKC; kc++) {
        CP_WAIT(1);
        __syncthreads();

        if (kc + 2 < NKC) {
            const uint32_t sb = ub + wslot * STG_B;
            const int k0 = (kc + 2) * 32 + gofs;
            CP16(sb + TB_AH + s0, ga_h + k0);      CP16(sb + TB_AH + s1, ga_h + k0 + 8);
            CP16(sb + TB_AL + s0, ga_l + k0);      CP16(sb + TB_AL + s1, ga_l + k0 + 8);
            CP16(sb + TB_BH + s0, gb_h + k0);      CP16(sb + TB_BH + s1, gb_h + k0 + 8);
            CP16(sb + TB_BL + s0, gb_l + k0);      CP16(sb + TB_BL + s1, gb_l + k0 + 8);
        }
        CP_COMMIT();

        const uint32_t us = ub + slot * STG_B;
        #pragma unroll
        for (int ks = 0; ks < 2; ks++) {
            const int chunk = ks * 2 + lck;
            uint32_t afh[4][4], afl[4][4];
            uint32_t bfh[2][4], bfl[2][4];
            #pragma unroll
            for (int mt = 0; mt < 4; mt++) {
                const uint32_t off = swz(warp_m * 64 + mt * 16 + lrm, chunk);
                LDSM4(afh[mt], us + TB_AH + off);
                LDSM4(afl[mt], us + TB_AL + off);
            }
            #pragma unroll
            for (int np = 0; np < 2; np++) {
                const uint32_t off = swz(warp_n * 32 + np * 16 + lrm, chunk);
                LDSM4(bfh[np], us + TB_BH + off);
                LDSM4(bfl[np], us + TB_BL + off);
            }
            #pragma unroll
            for (int mt = 0; mt < 4; mt++) {
                #pragma unroll
                for (int nt = 0; nt < 4; nt++) {
                    const int np = nt >> 1, sel = nt & 1;
                    MMA_BF16(acc[mt][nt], afh[mt], bfh[np][sel], bfh[np][sel + 2]);
                    MMA_BF16(acc[mt][nt], afh[mt], bfl[np][sel], bfl[np][sel + 2]);
                    MMA_BF16(acc[mt][nt], afl[mt], bfh[np][sel], bfh[np][sel + 2]);
                }
            }
        }
        slot = (slot == 2) ? 0 : slot + 1;
        wslot = (wslot == 2) ? 0 : wslot + 1;
    }

    #pragma unroll
    for (int mt = 0; mt < 4; mt++) {
        #pragma unroll
        for (int nt = 0; nt < 4; nt++) {
            const int mrow = m0 + warp_m * 64 + mt * 16 + (lane >> 2);
            const int ncol = n0 + warp_n * 32 + nt * 8 + (lane & 3) * 2;
            if (mode == 1) {
                const float b0 = bias[ncol], b1 = bias[ncol + 1];
                float2 v0 = make_float2(acc[mt][nt][0] + b0, acc[mt][nt][1] + b1);
                float2 v1 = make_float2(acc[mt][nt][2] + b0, acc[mt][nt][3] + b1);
                *(float2*)(Cout + (size_t)mrow * D_ + ncol)       = v0;
                *(float2*)(Cout + (size_t)(mrow + 8) * D_ + ncol) = v1;
            } else {
                const int which = ncol >> 10;
                const int h = (ncol >> 6) & 15;
                const int e = ncol & 63;
                __nv_bfloat16* bhp = (which == 0 ? g_qh : which == 1 ? g_kh : g_vh);
                __nv_bfloat16* blp = (which == 0 ? g_ql : which == 1 ? g_kl : g_vl);
                #pragma unroll
                for (int half = 0; half < 2; half++) {
                    const int mr = mrow + half * 8;
                    const float a0 = acc[mt][nt][half * 2 + 0];
                    const float a1 = acc[mt][nt][half * 2 + 1];
                    const int b = mr >> 11, s = mr & 2047;
                    const size_t base = (((size_t)(b * H_ + h) * S_) + s) * HD_ + e;
                    const float h0f = __bfloat162float(__float2bfloat16(a0));
                    const float h1f = __bfloat162float(__float2bfloat16(a1));
                    *(uint32_t*)&bhp[base] = pack_bf16(a0, a1);
                    *(uint32_t*)&blp[base] = pack_bf16(a0 - h0f, a1 - h1f);
                }
            }
        }
    }
}

// ---------------------------------------------------------------------------
// MMA flash attention, KV tile = 64, K double-buffered (prefetch next tile),
// V single-buffered (latency hidden by QK+softmax). 2 barriers per tile.
// Block = 128 q rows of one (b,h); 256 thr / 8 warps; 2 CTAs/SM.
// ---------------------------------------------------------------------------
#define ATPAD 72
#define AKH0  0                         // K hi buf0 (also Q hi staging rows 0..127)
#define AKL0  (2 * 64 * ATPAD)          // K lo buf0 (also Q lo staging)
#define AVH   (4 * 64 * ATPAD)
#define AVL   (5 * 64 * ATPAD)
#define ATT_SMEM (6 * 64 * ATPAD * 2)   // 55296 bytes

__global__ __launch_bounds__(256, 2) void attn_mma_kernel()
{
    extern __shared__ __nv_bfloat16 sm[];
    const uint32_t uS = smem_to_u32(sm);
    const int qt  = (int)gridDim.x - 1 - (int)blockIdx.x;   // heavy blocks first
    const int bh  = blockIdx.y;
    const int tid = threadIdx.x;
    const int lane = tid & 31;
    const int wid  = tid >> 5;
    const int m0g = qt * 128;

    const __nv_bfloat16* Qh = g_qh + (size_t)bh * S_ * HD_;
    const __nv_bfloat16* Ql = g_ql + (size_t)bh * S_ * HD_;
    const __nv_bfloat16* Kh = g_kh + (size_t)bh * S_ * HD_;
    const __nv_bfloat16* Kl = g_kl + (size_t)bh * S_ * HD_;
    const __nv_bfloat16* Vh = g_vh + (size_t)bh * S_ * HD_;
    const __nv_bfloat16* Vl = g_vl + (size_t)bh * S_ * HD_;

    const int lrm  = lane & 15;
    const int lck  = (lane >> 4) * 8;

    // KV loader indices: 256 threads cover 64 rows x 4 chunk-pairs
    const int krow = tid >> 2;          // 0..63
    const int kseg = tid & 3;           // chunk pair (elems kseg*16 .. +15)
    const uint32_t kvo = 2u * (krow * ATPAD + kseg * 16);

    // ---- stage Q (128 rows) into K buf0+buf1 region, build Q fragments ----
    {
        const int row = tid >> 1, half = tid & 1;
        const __nv_bfloat16* q_h = Qh + (size_t)(m0g + row) * HD_ + half * 32;
        const __nv_bfloat16* q_l = Ql + (size_t)(m0g + row) * HD_ + half * 32;
        const uint32_t d = 2u * (row * ATPAD + half * 32);
        #pragma unroll
        for (int c = 0; c < 4; c++) {
            CP16(uS + 2*AKH0 + d + c * 16, q_h + c * 8);
            CP16(uS + 2*AKL0 + d + c * 16, q_l + c * 8);
        }
        CP_COMMIT();
        CP_WAIT(0);
        __syncthreads();
    }
    uint32_t aQh[4][4], aQl[4][4];
    #pragma unroll
    for (int dk = 0; dk < 4; dk++) {
        const uint32_t off = 2u * ((wid * 16 + lrm) * ATPAD + dk * 16 + lck);
        LDSM4(aQh[dk], uS + 2*AKH0 + off);
        LDSM4(aQl[dk], uS + 2*AKL0 + off);
    }
    __syncthreads();    // Q frag reads done before K(0) overwrites buf0

    // issue K tile 0 into buffer 0
    {
        const __nv_bfloat16* k_h = Kh + (size_t)krow * HD_ + kseg * 16;
        const __nv_bfloat16* k_l = Kl + (size_t)krow * HD_ + kseg * 16;
        CP16(uS + 2*AKH0 + kvo,      k_h);
        CP16(uS + 2*AKH0 + kvo + 16, k_h + 8);
        CP16(uS + 2*AKL0 + kvo,      k_l);
        CP16(uS + 2*AKL0 + kvo + 16, k_l + 8);
        CP_COMMIT();
    }

    float accO[8][4];
    #pragma unroll
    for (int i = 0; i < 8; i++)
        #pragma unroll
        for (int r = 0; r < 4; r++) accO[i][r] = 0.f;
    float m0s = -1e30f, m1s = -1e30f, l0s = 0.f, l1s = 0.f;

    const int r0g = m0g + wid * 16 + (lane >> 2);
    const int r1g = r0g + 8;
    const int ntiles = 2 * (qt + 1);

    for (int kt = 0; kt < ntiles; kt++) {
        const int j0 = kt * 64;
        const int kb = kt & 1;
        const uint32_t ukh = uS + 2u * (AKH0 + kb * 64 * ATPAD);
        const uint32_t ukl = uS + 2u * (AKL0 + kb * 64 * ATPAD);

        CP_WAIT(0);        // K(kt) landed (only group possibly pending)
        __syncthreads();   // #1: K visible to all warps; prev PV reads done

        // issue V(kt) [group], then K(kt+1) [group] into other K buffer
        {
            const __nv_bfloat16* v_h = Vh + (size_t)(j0 + krow) * HD_ + kseg * 16;
            const __nv_bfloat16* v_l = Vl + (size_t)(j0 + krow) * HD_ + kseg * 16;
            CP16(uS + 2*AVH + kvo,      v_h);
            CP16(uS + 2*AVH + kvo + 16, v_h + 8);
            CP16(uS + 2*AVL + kvo,      v_l);
            CP16(uS + 2*AVL + kvo + 16, v_l + 8);
            CP_COMMIT();
            if (kt + 1 < ntiles) {
                const int j1 = (kt + 1) * 64;
                const uint32_t nkh = uS + 2u * (AKH0 + (kb ^ 1) * 64 * ATPAD);
                const uint32_t nkl = uS + 2u * (AKL0 + (kb ^ 1) * 64 * ATPAD);
                const __nv_bfloat16* k_h = Kh + (size_t)(j1 + krow) * HD_ + kseg * 16;
                const __nv_bfloat16* k_l = Kl + (size_t)(j1 + krow) * HD_ + kseg * 16;
                CP16(nkh + kvo,      k_h);
                CP16(nkh + kvo + 16, k_h + 8);
                CP16(nkl + kvo,      k_l);
                CP16(nkl + kvo + 16, k_l + 8);
            }
            CP_COMMIT();
        }

        // ---- QK: S[16 x 64] per warp ----
        float accS[8][4];
        #pragma unroll
        for (int i = 0; i < 8; i++)
            #pragma unroll
            for (int r = 0; r < 4; r++) accS[i][r] = 0.f;

        #pragma unroll
        for (int dk = 0; dk < 4; dk++) {
            #pragma unroll
            for (int jc = 0; jc < 4; jc++) {
                uint32_t kh[4], kl[4];
                const uint32_t off = 2u * ((jc * 16 + lrm) * ATPAD + dk * 16 + lck);
                LDSM4(kh, ukh + off);
                LDSM4(kl, ukl + off);
                MMA_BF16(accS[2*jc],   aQh[dk], kh[0], kh[2]);
                MMA_BF16(accS[2*jc+1], aQh[dk], kh[1], kh[3]);
                MMA_BF16(accS[2*jc],   aQh[dk], kl[0], kl[2]);
                MMA_BF16(accS[2*jc+1], aQh[dk], kl[1], kl[3]);
                MMA_BF16(accS[2*jc],   aQl[dk], kh[0], kh[2]);
                MMA_BF16(accS[2*jc+1], aQl[dk], kh[1], kh[3]);
            }
        }

        // ---- softmax (base-2, no MUFU) ----
        const bool diag = (kt >= 2 * qt);
        float mx0 = -1e30f, mx1 = -1e30f;
        #pragma unroll
        for (int nt = 0; nt < 8; nt++) {
            const int jb = j0 + nt * 8 + (lane & 3) * 2;
            float c0 = accS[nt][0] * SC2_;
            float c1 = accS[nt][1] * SC2_;
            float c2 = accS[nt][2] * SC2_;
            float c3 = accS[nt][3] * SC2_;
            if (diag) {
                if (jb     > r0g) c0 = -1e30f;
                if (jb + 1 > r0g) c1 = -1e30f;
                if (jb     > r1g) c2 = -1e30f;
                if (jb + 1 > r1g) c3 = -1e30f;
            }
            accS[nt][0] = c0; accS[nt][1] = c1; accS[nt][2] = c2; accS[nt][3] = c3;
            mx0 = fmaxf(mx0, fmaxf(c0, c1));
            mx1 = fmaxf(mx1, fmaxf(c2, c3));
        }
        mx0 = fmaxf(mx0, __shfl_xor_sync(0xffffffffu, mx0, 1));
        mx0 = fmaxf(mx0, __shfl_xor_sync(0xffffffffu, mx0, 2));
        mx1 = fmaxf(mx1, __shfl_xor_sync(0xffffffffu, mx1, 1));
        mx1 = fmaxf(mx1, __shfl_xor_sync(0xffffffffu, mx1, 2));

        const float mn0 = fmaxf(m0s, mx0);
        const float mn1 = fmaxf(m1s, mx1);
        const float al0 = exp2f_fast(m0s - mn0);
        const float al1 = exp2f_fast(m1s - mn1);
        m0s = mn0; m1s = mn1;

        float ls0 = 0.f, ls1 = 0.f;
        #pragma unroll
        for (int nt = 0; nt < 8; nt++) {
            float p0 = exp2f_fast(accS[nt][0] - mn0);
            float p1 = exp2f_fast(accS[nt][1] - mn0);
            float p2 = exp2f_fast(accS[nt][2] - mn1);
            float p3 = exp2f_fast(accS[nt][3] - mn1);
            accS[nt][0] = p0; accS[nt][1] = p1; accS[nt][2] = p2; accS[nt][3] = p3;
            ls0 += p0 + p1;
            ls1 += p2 + p3;
        }
        ls0 += __shfl_xor_sync(0xffffffffu, ls0, 1);
        ls0 += __shfl_xor_sync(0xffffffffu, ls0, 2);
        ls1 += __shfl_xor_sync(0xffffffffu, ls1, 1);
        ls1 += __shfl_xor_sync(0xffffffffu, ls1, 2);
        l0s = l0s * al0 + ls0;
        l1s = l1s * al1 + ls1;

        #pragma unroll
        for (int i = 0; i < 8; i++) {
            accO[i][0] *= al0; accO[i][1] *= al0;
            accO[i][2] *= al1; accO[i][3] *= al1;
        }

        CP_WAIT(1);        // V(kt) done (only K(kt+1) may still pend)
        __syncthreads();   // #2: V visible to all warps

        // ---- PV: accO += P @ V  (A-frags from accS; B via trans ldsm) ----
        #pragma unroll
        for (int kt2 = 0; kt2 < 4; kt2++) {
            uint32_t aPh[4], aPl[4];
            {
                const float p00 = accS[2*kt2][0],   p01 = accS[2*kt2][1];
                const float p02 = accS[2*kt2][2],   p03 = accS[2*kt2][3];
                const float p10 = accS[2*kt2+1][0], p11 = accS[2*kt2+1][1];
                const float p12 = accS[2*kt2+1][2], p13 = accS[2*kt2+1][3];
                aPh[0] = pack_bf16(p00, p01);
                aPh[1] = pack_bf16(p02, p03);
                aPh[2] = pack_bf16(p10, p11);
                aPh[3] = pack_bf16(p12, p13);
                aPl[0] = pack_bf16(p00 - __bfloat162float(__float2bfloat16(p00)),
                                   p01 - __bfloat162float(__float2bfloat16(p01)));
                aPl[1] = pack_bf16(p02 - __bfloat162float(__float2bfloat16(p02)),
                                   p03 - __bfloat162float(__float2bfloat16(p03)));
                aPl[2] = pack_bf16(p10 - __bfloat162float(__float2bfloat16(p10)),
                                   p11 - __bfloat162float(__float2bfloat16(p11)));
                aPl[3] = pack_bf16(p12 - __bfloat162float(__float2bfloat16(p12)),
                                   p13 - __bfloat162float(__float2bfloat16(p13)));
            }
            const uint32_t vbase = 2u * ((kt2 * 16 + lrm) * ATPAD + lck);
            #pragma unroll
            for (int g = 0; g < 4; g++) {
                uint32_t vh[4], vl[4];
                const uint32_t off = vbase + 2u * (g * 16);
                LDSM4T(vh, uS + 2*AVH + off);
                LDSM4T(vl, uS + 2*AVL + off);
                MMA_BF16(accO[2*g],   aPh, vh[0], vh[1]);
                MMA_BF16(accO[2*g+1], aPh, vh[2], vh[3]);
                MMA_BF16(accO[2*g],   aPh, vl[0], vl[1]);
                MMA_BF16(accO[2*g+1], aPh, vl[2], vl[3]);
                MMA_BF16(accO[2*g],   aPl, vh[0], vh[1]);
                MMA_BF16(accO[2*g+1], aPl, vh[2], vh[3]);
            }
        }
    }

    // ---- epilogue: normalize, split hi/lo, write concat layout ----
    const int b = bh >> 4;
    const int h = bh & 15;
    const float inv0 = 1.f / l0s;
    const float inv1 = 1.f / l1s;
    #pragma unroll
    for (int nt = 0; nt < 8; nt++) {
        const int e = nt * 8 + (lane & 3) * 2;
        #pragma unroll
        for (int half = 0; half < 2; half++) {
            const int s = (half == 0) ? r0g : r1g;
            const float sc = (half == 0) ? inv0 : inv1;
            const float a0 = accO[nt][half * 2 + 0] * sc;
            const float a1 = accO[nt][half * 2 + 1] * sc;
            const size_t base = ((size_t)b * S_ + s) * D_ + h * HD_ + e;
            const float h0f = __bfloat162float(__float2bfloat16(a0));
            const float h1f = __bfloat162float(__float2bfloat16(a1));
            *(uint32_t*)&g_atth[base] = pack_bf16(a0, a1);
            *(uint32_t*)&g_attl[base] = pack_bf16(a0 - h0f, a1 - h1f);
        }
    }
}

// ---------------------------------------------------------------------------
// Launch
// ---------------------------------------------------------------------------
extern "C" void kernel_launch(void* const* d_in, const int* in_sizes, int n_in,
                              void* d_out, int out_size)
{
    const float* x  = (const float*)d_in[0];
    const float* Wq = (const float*)d_in[1];
    const float* Wk = (const float*)d_in[2];
    const float* Wv = (const float*)d_in[3];
    const float* Wp = (const float*)d_in[4];
    const float* bp = (const float*)d_in[5];
    float* out = (float*)d_out;
    (void)in_sizes; (void)n_in; (void)out_size;

    cudaFuncSetAttribute(gemm_mma,
                         cudaFuncAttributeMaxDynamicSharedMemorySize, GEMM_SMEM);
    cudaFuncSetAttribute(attn_mma_kernel,
                         cudaFuncAttributeMaxDynamicSharedMemorySize, ATT_SMEM);

    const int x4 = (B_ * S_ * D_) / 4;
    split_kernel<<<(x4 + 255) / 256, 256>>>(x, 0, x4);
    convw_kernel<<<(3 * H_ * HD_ * D_) / 256, 256>>>(Wq, Wk, Wv);
    const int w4 = (D_ * D_) / 4;
    split_kernel<<<(w4 + 255) / 256, 256>>>(Wp, 2, w4);

    // QKV: C[4096, 3072], 128x128 tiles -> bf16 hi/lo q/k/v
    gemm_mma<<<dim3((3 * H_ * HD_) / 128, (B_ * S_) / 128), 256, GEMM_SMEM>>>(
        0, nullptr, nullptr);

    // MMA flash attention -> g_atth/g_attl
    attn_mma_kernel<<<dim3(S_ / 128, B_ * H_), 256, ATT_SMEM>>>();

    // out projection
    gemm_mma<<<dim3(D_ / 128, (B_ * S_) / 128), 256, GEMM_SMEM>>>(1, bp, out);
}

// round 14
// speedup vs baseline: 4.2348x; 1.2237x over previous
#include <cuda_runtime.h>
#include <cuda_bf16.h>
#include <math.h>
#include <cstdint>

// Problem constants: B=2, S=2048, D=1024, H=16, HD=64
#define B_  2
#define S_  2048
#define D_  1024
#define H_  16
#define HD_ 64
#define SC2_   0.045084220f       // D^-0.5 * log2(e)
#define KTOT 1024

// ---------------------------------------------------------------------------
// Scratch (device globals)
// ---------------------------------------------------------------------------
__device__ __nv_bfloat16 g_qh[(size_t)B_*H_*S_*HD_];
__device__ __nv_bfloat16 g_kh[(size_t)B_*H_*S_*HD_];
__device__ __nv_bfloat16 g_vh[(size_t)B_*H_*S_*HD_], g_vl[(size_t)B_*H_*S_*HD_];
__device__ __nv_bfloat16 g_atth[(size_t)B_*S_*D_], g_attl[(size_t)B_*S_*D_];
__device__ __nv_bfloat16 g_xh[(size_t)B_*S_*D_],  g_xl[(size_t)B_*S_*D_];
__device__ __nv_bfloat16 g_wbh[(size_t)3*H_*HD_*D_], g_wbl[(size_t)3*H_*HD_*D_];
__device__ __nv_bfloat16 g_wph[(size_t)D_*D_],    g_wpl[(size_t)D_*D_];

// ---------------------------------------------------------------------------
// PTX helpers (sm_80+ only; compile clean under compute_103)
// ---------------------------------------------------------------------------
__device__ __forceinline__ uint32_t smem_to_u32(const void* p) {
    uint32_t a;
    asm("{ .reg .u64 t; cvta.to.shared.u64 t, %1; cvt.u32.u64 %0, t; }" : "=r"(a) : "l"(p));
    return a;
}
#define LDSM4(r, addr) \
    asm volatile("ldmatrix.sync.aligned.m8n8.x4.shared.b16 {%0,%1,%2,%3}, [%4];" \
        : "=r"((r)[0]), "=r"((r)[1]), "=r"((r)[2]), "=r"((r)[3]) : "r"(addr))
#define LDSM4T(r, addr) \
    asm volatile("ldmatrix.sync.aligned.m8n8.x4.trans.shared.b16 {%0,%1,%2,%3}, [%4];" \
        : "=r"((r)[0]), "=r"((r)[1]), "=r"((r)[2]), "=r"((r)[3]) : "r"(addr))
#define MMA_BF16(c, a, b0, b1) \
    asm volatile("mma.sync.aligned.m16n8k16.row.col.f32.bf16.bf16.f32 " \
        "{%0,%1,%2,%3}, {%4,%5,%6,%7}, {%8,%9}, {%0,%1,%2,%3};" \
        : "+f"((c)[0]), "+f"((c)[1]), "+f"((c)[2]), "+f"((c)[3]) \
        : "r"((a)[0]), "r"((a)[1]), "r"((a)[2]), "r"((a)[3]), "r"(b0), "r"(b1))
#define CP16(saddr, gptr) \
    asm volatile("cp.async.cg.shared.global [%0], [%1], 16;" \
        :: "r"((uint32_t)(saddr)), "l"(gptr))
#define CP_COMMIT() asm volatile("cp.async.commit_group;" ::: "memory")
#define CP_WAIT(n)  asm volatile("cp.async.wait_group %0;" :: "n"(n) : "memory")

__device__ __forceinline__ uint32_t pack_bf16(float lo, float hi) {
    __nv_bfloat162 t = __floats2bfloat162_rn(lo, hi);
    return *(uint32_t*)&t;
}
// fast exp2: rint split + deg-5 poly; input always <= 0.
__device__ __forceinline__ float exp2f_fast(float t) {
    t = fmaxf(t, -120.f);
    int ni = __float2int_rn(t);
    float f = t - (float)ni;
    float r = 1.f + f * (0.69314718f + f * (0.24022651f + f * (0.05550411f
               + f * (0.00961812f + f * 0.00133336f))));
    return r * __int_as_float((ni + 127) << 23);
}

// ---------------------------------------------------------------------------
// Split kernels: fp32 -> bf16 hi + bf16 residual
// ---------------------------------------------------------------------------
__global__ __launch_bounds__(256) void split_kernel(const float* __restrict__ src,
                                                    int mode, int n4)
{
    int i = blockIdx.x * 256 + threadIdx.x;
    if (i >= n4) return;
    __nv_bfloat16* dh = (mode == 0) ? g_xh : g_wph;
    __nv_bfloat16* dl = (mode == 0) ? g_xl : g_wpl;

    float4 v = ((const float4*)src)[i];
    __nv_bfloat16 h0 = __float2bfloat16(v.x);
    __nv_bfloat16 h1 = __float2bfloat16(v.y);
    __nv_bfloat16 h2 = __float2bfloat16(v.z);
    __nv_bfloat16 h3 = __float2bfloat16(v.w);
    __nv_bfloat16 l0 = __float2bfloat16(v.x - __bfloat162float(h0));
    __nv_bfloat16 l1 = __float2bfloat16(v.y - __bfloat162float(h1));
    __nv_bfloat16 l2 = __float2bfloat16(v.z - __bfloat162float(h2));
    __nv_bfloat16 l3 = __float2bfloat16(v.w - __bfloat162float(h3));
    __nv_bfloat16 hs[4] = {h0, h1, h2, h3};
    __nv_bfloat16 ls[4] = {l0, l1, l2, l3};
    ((uint2*)dh)[i] = *(uint2*)hs;
    ((uint2*)dl)[i] = *(uint2*)ls;
}

__global__ __launch_bounds__(256) void convw_kernel(const float* __restrict__ Wq,
                                                    const float* __restrict__ Wk,
                                                    const float* __restrict__ Wv)
{
    size_t idx = (size_t)blockIdx.x * 256 + threadIdx.x;
    int n = (int)(idx >> 10);
    int k = (int)(idx & 1023);
    int which = n >> 10;
    int h = (n >> 6) & 15;
    int e = n & 63;
    const float* W = (which == 0 ? Wq : which == 1 ? Wk : Wv);
    float v = W[((size_t)h * D_ + k) * HD_ + e];
    __nv_bfloat16 hi = __float2bfloat16(v);
    __nv_bfloat16 lo = __float2bfloat16(v - __bfloat162float(hi));
    g_wbh[idx] = hi;
    g_wbl[idx] = lo;
}

// ---------------------------------------------------------------------------
// Warp-MMA GEMM, cp.async 3-stage pipeline.
// Per-block precision: p3 ? bf16x3 split : plain bf16 (q/k blocks only —
// softmax scale 1/32 makes score precision cheap; see round-13 analysis).
// mode 0: QKV (emit q/k hi only, v hi/lo)   mode 1: out-proj (+bias, fp32)
// ---------------------------------------------------------------------------
#define NST 3
#define TB_AH 0
#define TB_AL 8192
#define TB_BH 16384
#define TB_BL 24576
#define STG_B 32768
#define GEMM_SMEM (NST * STG_B)   // 98304

__device__ __forceinline__ uint32_t swz(int row, int chunk) {
    int sw = chunk ^ ((row >> 1) & 3) ^ ((row >> 3) & 1);
    return (uint32_t)((row << 6) + (sw << 4));
}

__global__ __launch_bounds__(256, 2) void gemm_mma(int mode,
                                                   const float* __restrict__ bias,
                                                   float* __restrict__ Cout)
{
    extern __shared__ __nv_bfloat16 dsm[];
    const uint32_t ub = smem_to_u32(dsm);

    const int tid  = threadIdx.x;
    const int lane = tid & 31;
    const int wid  = tid >> 5;
    const int warp_m = wid >> 2;
    const int warp_n = wid & 3;
    const int n0 = blockIdx.x * 128;
    const int m0 = blockIdx.y * 128;
    // q/k blocks (mode 0, nb<16) use 1-pass bf16; v and proj use 3-pass split
    const bool p3 = (mode == 1) || (blockIdx.x >= 16);

    const __nv_bfloat16* Ah = mode ? g_atth : g_xh;
    const __nv_bfloat16* Al = mode ? g_attl : g_xl;
    const __nv_bfloat16* Bh = mode ? g_wph  : g_wbh;
    const __nv_bfloat16* Bl = mode ? g_wpl  : g_wbl;

    const int lrow = tid >> 1;
    const int lseg = tid & 1;
    const __nv_bfloat16* ga_h = Ah + (size_t)(m0 + lrow) * KTOT;
    const __nv_bfloat16* ga_l = Al + (size_t)(m0 + lrow) * KTOT;
    const __nv_bfloat16* gb_h = Bh + (size_t)(n0 + lrow) * KTOT;
    const __nv_bfloat16* gb_l = Bl + (size_t)(n0 + lrow) * KTOT;
    const uint32_t s0 = swz(lrow, 2 * lseg);
    const uint32_t s1 = swz(lrow, 2 * lseg + 1);
    const int gofs = lseg * 16;

    const int lrm = lane & 15;
    const int lck = (lane >> 4);

    float acc[4][4][4];
    #pragma unroll
    for (int i = 0; i < 4; i++)
        #pragma unroll
        for (int j = 0; j < 4; j++)
            #pragma unroll
            for (int r = 0; r < 4; r++) acc[i][j][r] = 0.f;

    #pragma unroll
    for (int ps = 0; ps < 2; ps++) {
        const uint32_t sb = ub + ps * STG_B;
        const int k0 = ps * 32 + gofs;
        CP16(sb + TB_AH + s0, ga_h + k0);      CP16(sb + TB_AH + s1, ga_h + k0 + 8);
        CP16(sb + TB_BH + s0, gb_h + k0);      CP16(sb + TB_BH + s1, gb_h + k0 + 8);
        if (p3) {
            CP16(sb + TB_AL + s0, ga_l + k0);  CP16(sb + TB_AL + s1, ga_l + k0 + 8);
            CP16(sb + TB_BL + s0, gb_l + k0);  CP16(sb + TB_BL + s1, gb_l + k0 + 8);
        }
        CP_COMMIT();
    }

    const int NKC = KTOT / 32;
    int slot = 0, wslot = 2;
    for (int kc = 0; kc < NKC; kc++) {
        CP_WAIT(1);
        __syncthreads();

        if (kc + 2 < NKC) {
            const uint32_t sb = ub + wslot * STG_B;
            const int k0 = (kc + 2) * 32 + gofs;
            CP16(sb + TB_AH + s0, ga_h + k0);      CP16(sb + TB_AH + s1, ga_h + k0 + 8);
            CP16(sb + TB_BH + s0, gb_h + k0);      CP16(sb + TB_BH + s1, gb_h + k0 + 8);
            if (p3) {
                CP16(sb + TB_AL + s0, ga_l + k0);  CP16(sb + TB_AL + s1, ga_l + k0 + 8);
                CP16(sb + TB_BL + s0, gb_l + k0);  CP16(sb + TB_BL + s1, gb_l + k0 + 8);
            }
        }
        CP_COMMIT();

        const uint32_t us = ub + slot * STG_B;
        #pragma unroll
        for (int ks = 0; ks < 2; ks++) {
            const int chunk = ks * 2 + lck;
            uint32_t afh[4][4], afl[4][4];
            uint32_t bfh[2][4], bfl[2][4];
            #pragma unroll
            for (int mt = 0; mt < 4; mt++) {
                const uint32_t off = swz(warp_m * 64 + mt * 16 + lrm, chunk);
                LDSM4(afh[mt], us + TB_AH + off);
                if (p3) LDSM4(afl[mt], us + TB_AL + off);
            }
            #pragma unroll
            for (int np = 0; np < 2; np++) {
                const uint32_t off = swz(warp_n * 32 + np * 16 + lrm, chunk);
                LDSM4(bfh[np], us + TB_BH + off);
                if (p3) LDSM4(bfl[np], us + TB_BL + off);
            }
            #pragma unroll
            for (int mt = 0; mt < 4; mt++) {
                #pragma unroll
                for (int nt = 0; nt < 4; nt++) {
                    const int np = nt >> 1, sel = nt & 1;
                    MMA_BF16(acc[mt][nt], afh[mt], bfh[np][sel], bfh[np][sel + 2]);
                    if (p3) {
                        MMA_BF16(acc[mt][nt], afh[mt], bfl[np][sel], bfl[np][sel + 2]);
                        MMA_BF16(acc[mt][nt], afl[mt], bfh[np][sel], bfh[np][sel + 2]);
                    }
                }
            }
        }
        slot = (slot == 2) ? 0 : slot + 1;
        wslot = (wslot == 2) ? 0 : wslot + 1;
    }

    // ------------------------------ epilogue ------------------------------
    #pragma unroll
    for (int mt = 0; mt < 4; mt++) {
        #pragma unroll
        for (int nt = 0; nt < 4; nt++) {
            const int mrow = m0 + warp_m * 64 + mt * 16 + (lane >> 2);
            const int ncol = n0 + warp_n * 32 + nt * 8 + (lane & 3) * 2;
            if (mode == 1) {
                const float b0 = bias[ncol], b1 = bias[ncol + 1];
                float2 v0 = make_float2(acc[mt][nt][0] + b0, acc[mt][nt][1] + b1);
                float2 v1 = make_float2(acc[mt][nt][2] + b0, acc[mt][nt][3] + b1);
                *(float2*)(Cout + (size_t)mrow * D_ + ncol)       = v0;
                *(float2*)(Cout + (size_t)(mrow + 8) * D_ + ncol) = v1;
            } else {
                const int which = ncol >> 10;
                const int h = (ncol >> 6) & 15;
                const int e = ncol & 63;
                __nv_bfloat16* bhp = (which == 0 ? g_qh : which == 1 ? g_kh : g_vh);
                #pragma unroll
                for (int half = 0; half < 2; half++) {
                    const int mr = mrow + half * 8;
                    const float a0 = acc[mt][nt][half * 2 + 0];
                    const float a1 = acc[mt][nt][half * 2 + 1];
                    const int b = mr >> 11, s = mr & 2047;
                    const size_t base = (((size_t)(b * H_ + h) * S_) + s) * HD_ + e;
                    *(uint32_t*)&bhp[base] = pack_bf16(a0, a1);
                    if (which == 2) {   // v needs the residual too
                        const float h0f = __bfloat162float(__float2bfloat16(a0));
                        const float h1f = __bfloat162float(__float2bfloat16(a1));
                        *(uint32_t*)&g_vl[base] = pack_bf16(a0 - h0f, a1 - h1f);
                    }
                }
            }
        }
    }
}

// ---------------------------------------------------------------------------
// MMA flash attention, KV tile = 64. Q/K plain bf16 (1-pass QK — softmax
// damping), V + P keep bf16x3 (output-accuracy critical). K double-buffered.
// Block = 128 q rows of one (b,h); 256 thr / 8 warps; 2 CTAs/SM.
// ---------------------------------------------------------------------------
#define ATPAD 72
#define AKH0  0                         // K hi buf0 (Q staging rows 0..63)
#define AKH1  (64 * ATPAD)              // K hi buf1 (Q staging rows 64..127)
#define AVH   (2 * 64 * ATPAD)
#define AVL   (3 * 64 * ATPAD)
#define ATT_SMEM (4 * 64 * ATPAD * 2)   // 36864 bytes

__global__ __launch_bounds__(256, 2) void attn_mma_kernel()
{
    extern __shared__ __nv_bfloat16 sm[];
    const uint32_t uS = smem_to_u32(sm);
    const int qt  = (int)gridDim.x - 1 - (int)blockIdx.x;   // heavy blocks first
    const int bh  = blockIdx.y;
    const int tid = threadIdx.x;
    const int lane = tid & 31;
    const int wid  = tid >> 5;
    const int m0g = qt * 128;

    const __nv_bfloat16* Qh = g_qh + (size_t)bh * S_ * HD_;
    const __nv_bfloat16* Kh = g_kh + (size_t)bh * S_ * HD_;
    const __nv_bfloat16* Vh = g_vh + (size_t)bh * S_ * HD_;
    const __nv_bfloat16* Vl = g_vl + (size_t)bh * S_ * HD_;

    const int lrm  = lane & 15;
    const int lck  = (lane >> 4) * 8;

    // KV loader indices: 256 threads cover 64 rows x 4 chunk-pairs
    const int krow = tid >> 2;          // 0..63
    const int kseg = tid & 3;           // chunk pair (elems kseg*16 .. +15)
    const uint32_t kvo = 2u * (krow * ATPAD + kseg * 16);

    // ---- stage Q (128 rows) across both K bufs, build Q fragments ----
    {
        const int row = tid >> 1, half = tid & 1;
        const __nv_bfloat16* q_h = Qh + (size_t)(m0g + row) * HD_ + half * 32;
        const uint32_t d = 2u * (row * ATPAD + half * 32);
        #pragma unroll
        for (int c = 0; c < 4; c++)
            CP16(uS + d + c * 16, q_h + c * 8);
        CP_COMMIT();
        CP_WAIT(0);
        __syncthreads();
    }
    uint32_t aQh[4][4];
    #pragma unroll
    for (int dk = 0; dk < 4; dk++) {
        const uint32_t off = 2u * ((wid * 16 + lrm) * ATPAD + dk * 16 + lck);
        LDSM4(aQh[dk], uS + off);
    }
    __syncthreads();    // Q frag reads done before K(0) overwrites buf0

    // issue K tile 0 into buffer 0
    {
        const __nv_bfloat16* k_h = Kh + (size_t)krow * HD_ + kseg * 16;
        CP16(uS + 2*AKH0 + kvo,      k_h);
        CP16(uS + 2*AKH0 + kvo + 16, k_h + 8);
        CP_COMMIT();
    }

    float accO[8][4];
    #pragma unroll
    for (int i = 0; i < 8; i++)
        #pragma unroll
        for (int r = 0; r < 4; r++) accO[i][r] = 0.f;
    float m0s = -1e30f, m1s = -1e30f, l0s = 0.f, l1s = 0.f;

    const int r0g = m0g + wid * 16 + (lane >> 2);
    const int r1g = r0g + 8;
    const int ntiles = 2 * (qt + 1);

    for (int kt = 0; kt < ntiles; kt++) {
        const int j0 = kt * 64;
        const int kb = kt & 1;
        const uint32_t ukh = uS + 2u * (kb ? AKH1 : AKH0);

        CP_WAIT(0);        // K(kt) landed (only group possibly pending)
        __syncthreads();   // #1: K visible; prev PV reads done

        // issue V(kt) [group], then K(kt+1) [group] into other K buffer
        {
            const __nv_bfloat16* v_h = Vh + (size_t)(j0 + krow) * HD_ + kseg * 16;
            const __nv_bfloat16* v_l = Vl + (size_t)(j0 + krow) * HD_ + kseg * 16;
            CP16(uS + 2*AVH + kvo,      v_h);
            CP16(uS + 2*AVH + kvo + 16, v_h + 8);
            CP16(uS + 2*AVL + kvo,      v_l);
            CP16(uS + 2*AVL + kvo + 16, v_l + 8);
            CP_COMMIT();
            if (kt + 1 < ntiles) {
                const int j1 = (kt + 1) * 64;
                const uint32_t nkh = uS + 2u * (kb ? AKH0 : AKH1);
                const __nv_bfloat16* k_h = Kh + (size_t)(j1 + krow) * HD_ + kseg * 16;
                CP16(nkh + kvo,      k_h);
                CP16(nkh + kvo + 16, k_h + 8);
            }
            CP_COMMIT();
        }

        // ---- QK (1-pass bf16): S[16 x 64] per warp ----
        float accS[8][4];
        #pragma unroll
        for (int i = 0; i < 8; i++)
            #pragma unroll
            for (int r = 0; r < 4; r++) accS[i][r] = 0.f;

        #pragma unroll
        for (int dk = 0; dk < 4; dk++) {
            #pragma unroll
            for (int jc = 0; jc < 4; jc++) {
                uint32_t kh[4];
                const uint32_t off = 2u * ((jc * 16 + lrm) * ATPAD + dk * 16 + lck);
                LDSM4(kh, ukh + off);
                MMA_BF16(accS[2*jc],   aQh[dk], kh[0], kh[2]);
                MMA_BF16(accS[2*jc+1], aQh[dk], kh[1], kh[3]);
            }
        }

        // ---- softmax (base-2, no MUFU) ----
        const bool diag = (kt >= 2 * qt);
        float mx0 = -1e30f, mx1 = -1e30f;
        #pragma unroll
        for (int nt = 0; nt < 8; nt++) {
            const int jb = j0 + nt * 8 + (lane & 3) * 2;
            float c0 = accS[nt][0] * SC2_;
            float c1 = accS[nt][1] * SC2_;
            float c2 = accS[nt][2] * SC2_;
            float c3 = accS[nt][3] * SC2_;
            if (diag) {
                if (jb     > r0g) c0 = -1e30f;
                if (jb + 1 > r0g) c1 = -1e30f;
                if (jb     > r1g) c2 = -1e30f;
                if (jb + 1 > r1g) c3 = -1e30f;
            }
            accS[nt][0] = c0; accS[nt][1] = c1; accS[nt][2] = c2; accS[nt][3] = c3;
            mx0 = fmaxf(mx0, fmaxf(c0, c1));
            mx1 = fmaxf(mx1, fmaxf(c2, c3));
        }
        mx0 = fmaxf(mx0, __shfl_xor_sync(0xffffffffu, mx0, 1));
        mx0 = fmaxf(mx0, __shfl_xor_sync(0xffffffffu, mx0, 2));
        mx1 = fmaxf(mx1, __shfl_xor_sync(0xffffffffu, mx1, 1));
        mx1 = fmaxf(mx1, __shfl_xor_sync(0xffffffffu, mx1, 2));

        const float mn0 = fmaxf(m0s, mx0);
        const float mn1 = fmaxf(m1s, mx1);
        const float al0 = exp2f_fast(m0s - mn0);
        const float al1 = exp2f_fast(m1s - mn1);
        m0s = mn0; m1s = mn1;

        float ls0 = 0.f, ls1 = 0.f;
        #pragma unroll
        for (int nt = 0; nt < 8; nt++) {
            float p0 = exp2f_fast(accS[nt][0] - mn0);
            float p1 = exp2f_fast(accS[nt][1] - mn0);
            float p2 = exp2f_fast(accS[nt][2] - mn1);
            float p3v = exp2f_fast(accS[nt][3] - mn1);
            accS[nt][0] = p0; accS[nt][1] = p1; accS[nt][2] = p2; accS[nt][3] = p3v;
            ls0 += p0 + p1;
            ls1 += p2 + p3v;
        }
        ls0 += __shfl_xor_sync(0xffffffffu, ls0, 1);
        ls0 += __shfl_xor_sync(0xffffffffu, ls0, 2);
        ls1 += __shfl_xor_sync(0xffffffffu, ls1, 1);
        ls1 += __shfl_xor_sync(0xffffffffu, ls1, 2);
        l0s = l0s * al0 + ls0;
        l1s = l1s * al1 + ls1;

        #pragma unroll
        for (int i = 0; i < 8; i++) {
            accO[i][0] *= al0; accO[i][1] *= al0;
            accO[i][2] *= al1; accO[i][3] *= al1;
        }

        CP_WAIT(1);        // V(kt) done (only K(kt+1) may still pend)
        __syncthreads();   // #2: V visible to all warps

        // ---- PV (3-pass split): accO += P @ V ----
        #pragma unroll
        for (int kt2 = 0; kt2 < 4; kt2++) {
            uint32_t aPh[4], aPl[4];
            {
                const float p00 = accS[2*kt2][0],   p01 = accS[2*kt2][1];
                const float p02 = accS[2*kt2][2],   p03 = accS[2*kt2][3];
                const float p10 = accS[2*kt2+1][0], p11 = accS[2*kt2+1][1];
                const float p12 = accS[2*kt2+1][2], p13 = accS[2*kt2+1][3];
                aPh[0] = pack_bf16(p00, p01);
                aPh[1] = pack_bf16(p02, p03);
                aPh[2] = pack_bf16(p10, p11);
                aPh[3] = pack_bf16(p12, p13);
                aPl[0] = pack_bf16(p00 - __bfloat162float(__float2bfloat16(p00)),
                                   p01 - __bfloat162float(__float2bfloat16(p01)));
                aPl[1] = pack_bf16(p02 - __bfloat162float(__float2bfloat16(p02)),
                                   p03 - __bfloat162float(__float2bfloat16(p03)));
                aPl[2] = pack_bf16(p10 - __bfloat162float(__float2bfloat16(p10)),
                                   p11 - __bfloat162float(__float2bfloat16(p11)));
                aPl[3] = pack_bf16(p12 - __bfloat162float(__float2bfloat16(p12)),
                                   p13 - __bfloat162float(__float2bfloat16(p13)));
            }
            const uint32_t vbase = 2u * ((kt2 * 16 + lrm) * ATPAD + lck);
            #pragma unroll
            for (int g = 0; g < 4; g++) {
                uint32_t vh[4], vl[4];
                const uint32_t off = vbase + 2u * (g * 16);
                LDSM4T(vh, uS + 2*AVH + off);
                LDSM4T(vl, uS + 2*AVL + off);
                MMA_BF16(accO[2*g],   aPh, vh[0], vh[1]);
                MMA_BF16(accO[2*g+1], aPh, vh[2], vh[3]);
                MMA_BF16(accO[2*g],   aPh, vl[0], vl[1]);
                MMA_BF16(accO[2*g+1], aPh, vl[2], vl[3]);
                MMA_BF16(accO[2*g],   aPl, vh[0], vh[1]);
                MMA_BF16(accO[2*g+1], aPl, vh[2], vh[3]);
            }
        }
    }

    // ---- epilogue: normalize, split hi/lo, write concat layout ----
    const int b = bh >> 4;
    const int h = bh & 15;
    const float inv0 = 1.f / l0s;
    const float inv1 = 1.f / l1s;
    #pragma unroll
    for (int nt = 0; nt < 8; nt++) {
        const int e = nt * 8 + (lane & 3) * 2;
        #pragma unroll
        for (int half = 0; half < 2; half++) {
            const int s = (half == 0) ? r0g : r1g;
            const float sc = (half == 0) ? inv0 : inv1;
            const float a0 = accO[nt][half * 2 + 0] * sc;
            const float a1 = accO[nt][half * 2 + 1] * sc;
            const size_t base = ((size_t)b * S_ + s) * D_ + h * HD_ + e;
            const float h0f = __bfloat162float(__float2bfloat16(a0));
            const float h1f = __bfloat162float(__float2bfloat16(a1));
            *(uint32_t*)&g_atth[base] = pack_bf16(a0, a1);
            *(uint32_t*)&g_attl[base] = pack_bf16(a0 - h0f, a1 - h1f);
        }
    }
}

// ---------------------------------------------------------------------------
// Launch
// ---------------------------------------------------------------------------
extern "C" void kernel_launch(void* const* d_in, const int* in_sizes, int n_in,
                              void* d_out, int out_size)
{
    const float* x  = (const float*)d_in[0];
    const float* Wq = (const float*)d_in[1];
    const float* Wk = (const float*)d_in[2];
    const float* Wv = (const float*)d_in[3];
    const float* Wp = (const float*)d_in[4];
    const float* bp = (const float*)d_in[5];
    float* out = (float*)d_out;
    (void)in_sizes; (void)n_in; (void)out_size;

    cudaFuncSetAttribute(gemm_mma,
                         cudaFuncAttributeMaxDynamicSharedMemorySize, GEMM_SMEM);
    cudaFuncSetAttribute(attn_mma_kernel,
                         cudaFuncAttributeMaxDynamicSharedMemorySize, ATT_SMEM);

    const int x4 = (B_ * S_ * D_) / 4;
    split_kernel<<<(x4 + 255) / 256, 256>>>(x, 0, x4);
    convw_kernel<<<(3 * H_ * HD_ * D_) / 256, 256>>>(Wq, Wk, Wv);
    const int w4 = (D_ * D_) / 4;
    split_kernel<<<(w4 + 255) / 256, 256>>>(Wp, 2, w4);

    // QKV: C[4096, 3072], 128x128 tiles -> bf16 q/k (hi), v (hi/lo)
    gemm_mma<<<dim3((3 * H_ * HD_) / 128, (B_ * S_) / 128), 256, GEMM_SMEM>>>(
        0, nullptr, nullptr);

    // MMA flash attention -> g_atth/g_attl
    attn_mma_kernel<<<dim3(S_ / 128, B_ * H_), 256, ATT_SMEM>>>();

    // out projection
    gemm_mma<<<dim3(D_ / 128, (B_ * S_) / 128), 256, GEMM_SMEM>>>(1, bp, out);
}